// round 2
// baseline (speedup 1.0000x reference)
#include <cuda_runtime.h>
#include <math.h>

#define BATCH 2
#define SEQ   2048
#define DIM   1024
#define NH    16
#define HD    64
#define NBLK  32   // SEQ / 64
#define BS    64

// Scratch (allocation-free rule: device globals)
__device__ float g_Q[BATCH * SEQ * DIM];
__device__ float g_K[BATCH * SEQ * DIM];
__device__ float g_V[BATCH * SEQ * DIM];
__device__ float g_O[BATCH * SEQ * DIM];
__device__ unsigned char g_bm[NBLK * NBLK];   // block-level mask (32x32)

// Build the 32x32 block mask from the token-level mask, auto-detecting the
// element size of the uploaded bool array. Element (0,1) is guaranteed true
// (row 0 is global in BigBird), so byte 1 of the buffer discriminates:
//   1-byte bool  -> m[1] == 1
//   int32/f32    -> m[1] == 0   (01 00 00 00 / 00 00 80 3F)
//   bf16/fp16    -> m[1] == 0x3F / 0x3C
__global__ void build_block_mask(const unsigned char* __restrict__ m)
{
    const unsigned char b1 = m[1];
    int esz = (b1 == 0) ? 4 : (b1 == 1 ? 1 : 2);

    int idx = blockIdx.x * blockDim.x + threadIdx.x;   // 0..1023
    if (idx >= NBLK * NBLK) return;
    int qb = idx / NBLK, kb = idx % NBLK;
    size_t elem = (size_t)(qb * BS) * SEQ + (size_t)kb * BS;   // token (qb*64, kb*64)

    bool allowed;
    if (esz == 1) {
        allowed = m[elem] != 0;
    } else if (esz == 2) {
        allowed = ((const unsigned short*)m)[elem] != 0;
    } else {
        allowed = ((const unsigned int*)m)[elem] != 0;  // covers int32 and float32 (0.0f == 0x0)
    }
    g_bm[idx] = allowed ? 1 : 0;
}

// C[m][n] = sum_k A[m][k] * W[n][k]   (Linear: x @ W^T), all row-major.
// 64x64 output tile, KT=16, 16x16 threads, 4x4 accumulators per thread.
__global__ void sgemm_nt(const float* __restrict__ A, const float* __restrict__ W,
                         float* __restrict__ C, int M, int N, int K)
{
    __shared__ float As[64][17];
    __shared__ float Bs[64][17];
    const int tx = threadIdx.x;            // 0..15
    const int ty = threadIdx.y;            // 0..15
    const int tid = ty * 16 + tx;
    const int m0 = blockIdx.y * 64;
    const int n0 = blockIdx.x * 64;

    float acc[4][4];
#pragma unroll
    for (int i = 0; i < 4; i++)
#pragma unroll
        for (int j = 0; j < 4; j++) acc[i][j] = 0.f;

    for (int k0 = 0; k0 < K; k0 += 16) {
#pragma unroll
        for (int i = 0; i < 4; i++) {
            int idx = tid + i * 256;       // 1024 elements = 64x16
            int r = idx >> 4, c = idx & 15;
            As[r][c] = A[(size_t)(m0 + r) * K + k0 + c];
            Bs[r][c] = W[(size_t)(n0 + r) * K + k0 + c];
        }
        __syncthreads();
#pragma unroll
        for (int kk = 0; kk < 16; kk++) {
            float a[4], b[4];
#pragma unroll
            for (int i = 0; i < 4; i++) a[i] = As[ty * 4 + i][kk];
#pragma unroll
            for (int j = 0; j < 4; j++) b[j] = Bs[tx * 4 + j][kk];
#pragma unroll
            for (int i = 0; i < 4; i++)
#pragma unroll
                for (int j = 0; j < 4; j++) acc[i][j] += a[i] * b[j];
        }
        __syncthreads();
    }
#pragma unroll
    for (int i = 0; i < 4; i++)
#pragma unroll
        for (int j = 0; j < 4; j++)
            C[(size_t)(m0 + ty * 4 + i) * N + n0 + tx * 4 + j] = acc[i][j];
}

// Block-sparse flash attention.
// Q/K/V layout: [B, L, D], head h occupies columns [h*64, h*64+64).
// Grid: (qblock=32, head=16, batch=2). Block: 64 threads, one query per thread.
__global__ void bigbird_attn(const float* __restrict__ Q, const float* __restrict__ K,
                             const float* __restrict__ V,
                             float* __restrict__ O)
{
    const int qb = blockIdx.x;
    const int h  = blockIdx.y;
    const int b  = blockIdx.z;
    const int tid = threadIdx.x;           // 0..63

    __shared__ float Ks[64][64];
    __shared__ float Vs[64][64];
    __shared__ float Ss[64][64];           // Ss[key][query] — per-thread column

    const int qi = qb * BS + tid;
    const size_t qoff = ((size_t)(b * SEQ + qi)) * DIM + h * HD;

    float q[64], acc[64];
#pragma unroll
    for (int d = 0; d < 64; d++) { q[d] = Q[qoff + d]; acc[d] = 0.f; }
    float mrow = -INFINITY, lrow = 0.f;
    const float scale = 0.125f;            // 1/sqrt(64)

    for (int kb = 0; kb < NBLK; kb++) {
        if (!g_bm[qb * NBLK + kb]) continue;   // uniform across block

        __syncthreads();                   // protect Ks/Vs from previous iter's readers
        const size_t kbase = ((size_t)(b * SEQ + kb * BS)) * DIM + h * HD;
        for (int i = tid; i < 64 * 16; i += 64) {
            int r = i >> 4, c = i & 15;
            ((float4*)&Ks[r][0])[c] = *(const float4*)&K[kbase + (size_t)r * DIM + c * 4];
            ((float4*)&Vs[r][0])[c] = *(const float4*)&V[kbase + (size_t)r * DIM + c * 4];
        }
        __syncthreads();

        float mblk = -INFINITY;
#pragma unroll 4
        for (int j = 0; j < 64; j++) {
            float s = 0.f;
#pragma unroll
            for (int d = 0; d < 64; d += 4) {
                float4 kv = *(float4*)&Ks[j][d];  // broadcast across the warp
                s += q[d] * kv.x + q[d + 1] * kv.y + q[d + 2] * kv.z + q[d + 3] * kv.w;
            }
            s *= scale;
            Ss[j][tid] = s;
            mblk = fmaxf(mblk, s);
        }

        float mnew = fmaxf(mrow, mblk);
        float alpha = __expf(mrow - mnew); // exp(-inf)=0 on first live block
        lrow *= alpha;
#pragma unroll
        for (int d = 0; d < 64; d++) acc[d] *= alpha;
        mrow = mnew;

        for (int j = 0; j < 64; j++) {
            float p = __expf(Ss[j][tid] - mnew);
            lrow += p;
#pragma unroll
            for (int d = 0; d < 64; d += 4) {
                float4 vv = *(float4*)&Vs[j][d];  // broadcast
                acc[d]     += p * vv.x;
                acc[d + 1] += p * vv.y;
                acc[d + 2] += p * vv.z;
                acc[d + 3] += p * vv.w;
            }
        }
    }

    const float inv = 1.f / lrow;          // block 0 always allowed -> lrow > 0
#pragma unroll
    for (int d = 0; d < 64; d++) O[qoff + d] = acc[d] * inv;
}

extern "C" void kernel_launch(void* const* d_in, const int* in_sizes, int n_in,
                              void* d_out, int out_size)
{
    const float* X  = (const float*)d_in[0];
    const float* Wq = (const float*)d_in[1];
    const float* Wk = (const float*)d_in[2];
    const float* Wv = (const float*)d_in[3];
    const float* Wo = (const float*)d_in[4];
    const unsigned char* mask = (const unsigned char*)d_in[5];
    float* out = (float*)d_out;

    float *Qb, *Kb, *Vb, *Ob;
    cudaGetSymbolAddress((void**)&Qb, g_Q);
    cudaGetSymbolAddress((void**)&Kb, g_K);
    cudaGetSymbolAddress((void**)&Vb, g_V);
    cudaGetSymbolAddress((void**)&Ob, g_O);

    build_block_mask<<<1, 1024>>>(mask);

    const int M = BATCH * SEQ;             // 4096
    dim3 gblk(16, 16);
    dim3 ggrid(DIM / 64, M / 64);          // (16, 64)

    sgemm_nt<<<ggrid, gblk>>>(X, Wq, Qb, M, DIM, DIM);
    sgemm_nt<<<ggrid, gblk>>>(X, Wk, Kb, M, DIM, DIM);
    sgemm_nt<<<ggrid, gblk>>>(X, Wv, Vb, M, DIM, DIM);

    dim3 agrid(NBLK, NH, BATCH);           // (32, 16, 2)
    bigbird_attn<<<agrid, 64>>>(Qb, Kb, Vb, Ob);

    sgemm_nt<<<ggrid, gblk>>>(Ob, Wo, out, M, DIM, DIM);
}

// round 4
// speedup vs baseline: 1.5634x; 1.5634x over previous
#include <cuda_runtime.h>
#include <cuda_bf16.h>
#include <math.h>
#include <stdint.h>

#define BATCH 2
#define SEQ   2048
#define DIM   1024
#define NH    16
#define HD    64
#define NBLK  32
#define BS    64
#define MROWS (BATCH * SEQ)        // 4096
#define KTOT  3072                 // 3 x 1024 (hi|hi|lo split-K)
#define KCH   64                   // K per smem stage
#define NCHUNK (KTOT / KCH)        // 48
#define TM    128
#define TN    128
#define RSB   144                  // smem row stride bytes (64 bf16 + 8 pad)
#define STAGE_BYTES (128 * RSB)    // 18432
#define SM_TOTAL (4 * STAGE_BYTES) // A0,A1,B0,B1 = 73728

// ---------------- device scratch (allocation-free rule) ----------------
__device__ float g_Q[MROWS * DIM];
__device__ float g_K[MROWS * DIM];
__device__ float g_V[MROWS * DIM];
__device__ float g_O[MROWS * DIM];
__device__ __nv_bfloat16 g_Xc[(size_t)MROWS * KTOT];
__device__ __nv_bfloat16 g_Oc[(size_t)MROWS * KTOT];
__device__ __nv_bfloat16 g_Wc[4][(size_t)DIM * KTOT];
__device__ unsigned char g_bm[NBLK * NBLK];

// ---------------- helpers ----------------
__device__ __forceinline__ uint32_t smem_u32(const void* p) {
    uint32_t a;
    asm("{ .reg .u64 t; cvta.to.shared.u64 t, %1; cvt.u32.u64 %0, t; }" : "=r"(a) : "l"(p));
    return a;
}
#define LDSM_X4(r0, r1, r2, r3, addr) \
    asm volatile("ldmatrix.sync.aligned.m8n8.x4.shared.b16 {%0,%1,%2,%3}, [%4];" \
        : "=r"(r0), "=r"(r1), "=r"(r2), "=r"(r3) : "r"(addr))

__device__ __forceinline__ void mma16816(float* c, const uint32_t* a, uint32_t b0, uint32_t b1) {
    asm volatile("mma.sync.aligned.m16n8k16.row.col.f32.bf16.bf16.f32 "
        "{%0,%1,%2,%3}, {%4,%5,%6,%7}, {%8,%9}, {%0,%1,%2,%3};"
        : "+f"(c[0]), "+f"(c[1]), "+f"(c[2]), "+f"(c[3])
        : "r"(a[0]), "r"(a[1]), "r"(a[2]), "r"(a[3]), "r"(b0), "r"(b1));
}

// ---------------- mask build (dtype-agnostic) ----------------
__global__ void build_block_mask(const unsigned char* __restrict__ m)
{
    const unsigned char b1 = m[1];                 // element (0,1) is true
    int esz = (b1 == 0) ? 4 : (b1 == 1 ? 1 : 2);
    int idx = blockIdx.x * blockDim.x + threadIdx.x;
    if (idx >= NBLK * NBLK) return;
    int qb = idx / NBLK, kb = idx % NBLK;
    size_t elem = (size_t)(qb * BS) * SEQ + (size_t)kb * BS;
    bool allowed;
    if (esz == 1)      allowed = m[elem] != 0;
    else if (esz == 2) allowed = ((const unsigned short*)m)[elem] != 0;
    else               allowed = ((const unsigned int*)m)[elem] != 0;
    g_bm[idx] = allowed ? 1 : 0;
}

// ---------------- fp32 -> bf16 split conversions ----------------
__global__ void conv_act(const float* __restrict__ X, __nv_bfloat16* __restrict__ out, int rows)
{
    int i = blockIdx.x * blockDim.x + threadIdx.x;
    if (i >= rows * DIM) return;
    int r = i >> 10, c = i & 1023;
    float x = X[i];
    __nv_bfloat16 h = __float2bfloat16(x);
    __nv_bfloat16 l = __float2bfloat16(x - __bfloat162float(h));
    size_t base = (size_t)r * KTOT;
    out[base + c] = h;
    out[base + 1024 + c] = h;
    out[base + 2048 + c] = l;
}
__global__ void conv_wgt(const float* __restrict__ W, __nv_bfloat16* __restrict__ out)
{
    int i = blockIdx.x * blockDim.x + threadIdx.x;
    if (i >= DIM * DIM) return;
    int r = i >> 10, c = i & 1023;
    float x = W[i];
    __nv_bfloat16 h = __float2bfloat16(x);
    __nv_bfloat16 l = __float2bfloat16(x - __bfloat162float(h));
    size_t base = (size_t)r * KTOT;
    out[base + c] = h;
    out[base + 1024 + c] = l;
    out[base + 2048 + c] = h;
}

// ---------------- mma.sync GEMM: C[m][n] = sum_k A[m][k] * B[n][k] ----------------
// A: [MROWS,KTOT] bf16, Bw: [DIM,KTOT] bf16, C fp32. 128x128/CTA, 8 warps (2Mx4N),
// warp tile 64x32, m16n8k16 HMMA, double-buffered smem (144B padded rows).
__global__ void __launch_bounds__(256, 1)
gemm_mma(const __nv_bfloat16* __restrict__ A, const __nv_bfloat16* __restrict__ Bw,
         float* __restrict__ C)
{
    extern __shared__ char dsm[];
    const uint32_t sb = smem_u32(dsm);
    const int tid = threadIdx.x;
    const int wid = tid >> 5, l = tid & 31;
    const int wm = wid >> 2, wn = wid & 3;                 // warp 2x4
    const int m0 = blockIdx.y * TM, n0 = blockIdx.x * TN;

    // staging: thread covers row r, 4 x 16B chunks
    const int r = tid >> 1;
    const int cb = (tid & 1) * 4;                          // chunk base (16B units)
    const __nv_bfloat16* Ag = A + (size_t)(m0 + r) * KTOT;
    const __nv_bfloat16* Bg = Bw + (size_t)(n0 + r) * KTOT;
    char* sA = dsm;                                        // A stages at 0, 18432
    char* sB = dsm + 2 * STAGE_BYTES;                      // B stages

    float acc[4][4][4];
#pragma unroll
    for (int i = 0; i < 4; i++)
#pragma unroll
        for (int j = 0; j < 4; j++)
#pragma unroll
            for (int q = 0; q < 4; q++) acc[i][j][q] = 0.f;

    // ldmatrix per-lane offsets
    const uint32_t a_off = (uint32_t)((l & 15) * RSB + (l >> 4) * 16);
    const uint32_t b_off = (uint32_t)(((l & 7) + ((l >> 4) & 1) * 8) * RSB + ((l >> 3) & 1) * 16);

    uint4 sa[4], sbv[4];
    // prologue: chunk 0
#pragma unroll
    for (int q = 0; q < 4; q++) {
        sa[q]  = *(const uint4*)(Ag + (cb + q) * 8);
        sbv[q] = *(const uint4*)(Bg + (cb + q) * 8);
    }
#pragma unroll
    for (int q = 0; q < 4; q++) {
        *(uint4*)(sA + r * RSB + (cb + q) * 16) = sa[q];
        *(uint4*)(sB + r * RSB + (cb + q) * 16) = sbv[q];
    }
    __syncthreads();

    for (int i = 0; i < NCHUNK; i++) {
        if (i + 1 < NCHUNK) {
            const int k0 = (i + 1) * KCH;
#pragma unroll
            for (int q = 0; q < 4; q++) {
                sa[q]  = *(const uint4*)(Ag + k0 + (cb + q) * 8);
                sbv[q] = *(const uint4*)(Bg + k0 + (cb + q) * 8);
            }
        }

        const uint32_t abase = sb + (i & 1) * STAGE_BYTES + (uint32_t)(wm * 64) * RSB + a_off;
        const uint32_t bbase = sb + 2 * STAGE_BYTES + (i & 1) * STAGE_BYTES
                               + (uint32_t)(wn * 32) * RSB + b_off;
#pragma unroll
        for (int ks = 0; ks < 4; ks++) {
            uint32_t af[4][4], bf[2][4];
#pragma unroll
            for (int mt = 0; mt < 4; mt++)
                LDSM_X4(af[mt][0], af[mt][1], af[mt][2], af[mt][3],
                        abase + mt * (16 * RSB) + ks * 32);
#pragma unroll
            for (int g = 0; g < 2; g++)
                LDSM_X4(bf[g][0], bf[g][1], bf[g][2], bf[g][3],
                        bbase + g * (16 * RSB) + ks * 32);
#pragma unroll
            for (int mt = 0; mt < 4; mt++)
#pragma unroll
                for (int nt = 0; nt < 4; nt++)
                    mma16816(acc[mt][nt], af[mt], bf[nt >> 1][(nt & 1) * 2],
                             bf[nt >> 1][(nt & 1) * 2 + 1]);
        }

        if (i + 1 < NCHUNK) {
            const int s = (i + 1) & 1;
#pragma unroll
            for (int q = 0; q < 4; q++) {
                *(uint4*)(sA + s * STAGE_BYTES + r * RSB + (cb + q) * 16) = sa[q];
                *(uint4*)(sB + s * STAGE_BYTES + r * RSB + (cb + q) * 16) = sbv[q];
            }
        }
        __syncthreads();
    }

    // epilogue: acc[mt][nt] lane l -> rows l/4, l/4+8; cols 2*(l%4)+{0,1}
#pragma unroll
    for (int mt = 0; mt < 4; mt++) {
#pragma unroll
        for (int nt = 0; nt < 4; nt++) {
            const int mr = m0 + wm * 64 + mt * 16 + (l >> 2);
            const int nc = n0 + wn * 32 + nt * 8 + (l & 3) * 2;
            float2 v0 = make_float2(acc[mt][nt][0], acc[mt][nt][1]);
            float2 v1 = make_float2(acc[mt][nt][2], acc[mt][nt][3]);
            *(float2*)(C + (size_t)mr * DIM + nc)       = v0;
            *(float2*)(C + (size_t)(mr + 8) * DIM + nc) = v1;
        }
    }
}

// ---------------- block-sparse flash attention (fp32, unchanged) ----------------
__global__ void bigbird_attn(const float* __restrict__ Q, const float* __restrict__ K,
                             const float* __restrict__ V, float* __restrict__ O)
{
    const int qb = blockIdx.x;
    const int h  = blockIdx.y;
    const int b  = blockIdx.z;
    const int tid = threadIdx.x;

    __shared__ float Ks[64][64];
    __shared__ float Vs[64][64];
    __shared__ float Ss[64][64];

    const int qi = qb * BS + tid;
    const size_t qoff = ((size_t)(b * SEQ + qi)) * DIM + h * HD;

    float q[64], acc[64];
#pragma unroll
    for (int d = 0; d < 64; d++) { q[d] = Q[qoff + d]; acc[d] = 0.f; }
    float mrow = -INFINITY, lrow = 0.f;
    const float scale = 0.125f;

    for (int kb = 0; kb < NBLK; kb++) {
        if (!g_bm[qb * NBLK + kb]) continue;

        __syncthreads();
        const size_t kbase = ((size_t)(b * SEQ + kb * BS)) * DIM + h * HD;
        for (int i = tid; i < 64 * 16; i += 64) {
            int rr = i >> 4, c = i & 15;
            ((float4*)&Ks[rr][0])[c] = *(const float4*)&K[kbase + (size_t)rr * DIM + c * 4];
            ((float4*)&Vs[rr][0])[c] = *(const float4*)&V[kbase + (size_t)rr * DIM + c * 4];
        }
        __syncthreads();

        float mblk = -INFINITY;
#pragma unroll 4
        for (int j = 0; j < 64; j++) {
            float s = 0.f;
#pragma unroll
            for (int d = 0; d < 64; d += 4) {
                float4 kv = *(float4*)&Ks[j][d];
                s += q[d] * kv.x + q[d + 1] * kv.y + q[d + 2] * kv.z + q[d + 3] * kv.w;
            }
            s *= scale;
            Ss[j][tid] = s;
            mblk = fmaxf(mblk, s);
        }

        float mnew = fmaxf(mrow, mblk);
        float alpha = __expf(mrow - mnew);
        lrow *= alpha;
#pragma unroll
        for (int d = 0; d < 64; d++) acc[d] *= alpha;
        mrow = mnew;

        for (int j = 0; j < 64; j++) {
            float p = __expf(Ss[j][tid] - mnew);
            lrow += p;
#pragma unroll
            for (int d = 0; d < 64; d += 4) {
                float4 vv = *(float4*)&Vs[j][d];
                acc[d]     += p * vv.x;
                acc[d + 1] += p * vv.y;
                acc[d + 2] += p * vv.z;
                acc[d + 3] += p * vv.w;
            }
        }
    }

    const float inv = 1.f / lrow;
#pragma unroll
    for (int d = 0; d < 64; d++) O[qoff + d] = acc[d] * inv;
}

// ---------------- launcher ----------------
extern "C" void kernel_launch(void* const* d_in, const int* in_sizes, int n_in,
                              void* d_out, int out_size)
{
    const float* X  = (const float*)d_in[0];
    const float* Wq = (const float*)d_in[1];
    const float* Wk = (const float*)d_in[2];
    const float* Wv = (const float*)d_in[3];
    const float* Wo = (const float*)d_in[4];
    const unsigned char* mask = (const unsigned char*)d_in[5];
    float* out = (float*)d_out;

    float *Qb, *Kb, *Vb, *Ob;
    __nv_bfloat16 *Xc, *Oc, *Wc;
    cudaGetSymbolAddress((void**)&Qb, g_Q);
    cudaGetSymbolAddress((void**)&Kb, g_K);
    cudaGetSymbolAddress((void**)&Vb, g_V);
    cudaGetSymbolAddress((void**)&Ob, g_O);
    cudaGetSymbolAddress((void**)&Xc, g_Xc);
    cudaGetSymbolAddress((void**)&Oc, g_Oc);
    cudaGetSymbolAddress((void**)&Wc, g_Wc);

    cudaFuncSetAttribute(gemm_mma, cudaFuncAttributeMaxDynamicSharedMemorySize, SM_TOTAL);

    build_block_mask<<<1, 1024>>>(mask);

    conv_act<<<(MROWS * DIM + 255) / 256, 256>>>(X, Xc, MROWS);
    conv_wgt<<<(DIM * DIM + 255) / 256, 256>>>(Wq, Wc + 0 * (size_t)DIM * KTOT);
    conv_wgt<<<(DIM * DIM + 255) / 256, 256>>>(Wk, Wc + 1 * (size_t)DIM * KTOT);
    conv_wgt<<<(DIM * DIM + 255) / 256, 256>>>(Wv, Wc + 2 * (size_t)DIM * KTOT);
    conv_wgt<<<(DIM * DIM + 255) / 256, 256>>>(Wo, Wc + 3 * (size_t)DIM * KTOT);

    dim3 ggrid(DIM / TN, MROWS / TM);   // (8, 32)
    gemm_mma<<<ggrid, 256, SM_TOTAL>>>(Xc, Wc + 0 * (size_t)DIM * KTOT, Qb);
    gemm_mma<<<ggrid, 256, SM_TOTAL>>>(Xc, Wc + 1 * (size_t)DIM * KTOT, Kb);
    gemm_mma<<<ggrid, 256, SM_TOTAL>>>(Xc, Wc + 2 * (size_t)DIM * KTOT, Vb);

    dim3 agrid(NBLK, NH, BATCH);
    bigbird_attn<<<agrid, 64>>>(Qb, Kb, Vb, Ob);

    conv_act<<<(MROWS * DIM + 255) / 256, 256>>>(Ob, Oc, MROWS);
    gemm_mma<<<ggrid, 256, SM_TOTAL>>>(Oc, Wc + 3 * (size_t)DIM * KTOT, out);
}

// round 5
// speedup vs baseline: 2.5177x; 1.6104x over previous
#include <cuda_runtime.h>
#include <cuda_bf16.h>
#include <math.h>
#include <stdint.h>

#define BATCH 2
#define SEQ   2048
#define DIM   1024
#define NH    16
#define HD    64
#define NBLK  32
#define BS    64
#define MROWS (BATCH * SEQ)        // 4096
#define KTOT  3072                 // 3 x 1024 (hi|hi|lo split-K)
#define KCH   64
#define NCHUNK (KTOT / KCH)        // 48
#define TM    128
#define TN    128
#define RSB   144                  // GEMM smem row stride bytes
#define STAGE_BYTES (128 * RSB)
#define SM_TOTAL (4 * STAGE_BYTES)

// attention smem: 4 tiles of 64 rows x 192 bf16, row stride 400B
#define ARS   400
#define ATILE (64 * ARS)           // 25600
#define ASM_TOTAL (4 * ATILE)      // 102400

// ---------------- device scratch (allocation-free rule) ----------------
__device__ float g_Q[MROWS * DIM];
__device__ float g_K[MROWS * DIM];
__device__ float g_V[MROWS * DIM];
__device__ float g_O[MROWS * DIM];
__device__ __nv_bfloat16 g_Xc[(size_t)MROWS * KTOT];
__device__ __nv_bfloat16 g_Oc[(size_t)MROWS * KTOT];
__device__ __nv_bfloat16 g_Wc[4][(size_t)DIM * KTOT];
__device__ __nv_bfloat16 g_Qa[(size_t)BATCH * NH * SEQ * 192];   // [hi|hi|lo]
__device__ __nv_bfloat16 g_Ka[(size_t)BATCH * NH * SEQ * 192];   // [hi|lo|hi]
__device__ __nv_bfloat16 g_Va[(size_t)BATCH * NH * NBLK * 64 * 192]; // Vt [d,192j] [hi|lo|hi]
__device__ unsigned char g_bm[NBLK * NBLK];

// ---------------- helpers ----------------
__device__ __forceinline__ uint32_t smem_u32(const void* p) {
    uint32_t a;
    asm("{ .reg .u64 t; cvta.to.shared.u64 t, %1; cvt.u32.u64 %0, t; }" : "=r"(a) : "l"(p));
    return a;
}
#define LDSM_X4(r0, r1, r2, r3, addr) \
    asm volatile("ldmatrix.sync.aligned.m8n8.x4.shared.b16 {%0,%1,%2,%3}, [%4];" \
        : "=r"(r0), "=r"(r1), "=r"(r2), "=r"(r3) : "r"(addr))

__device__ __forceinline__ void mma16816(float* c, const uint32_t* a, uint32_t b0, uint32_t b1) {
    asm volatile("mma.sync.aligned.m16n8k16.row.col.f32.bf16.bf16.f32 "
        "{%0,%1,%2,%3}, {%4,%5,%6,%7}, {%8,%9}, {%0,%1,%2,%3};"
        : "+f"(c[0]), "+f"(c[1]), "+f"(c[2]), "+f"(c[3])
        : "r"(a[0]), "r"(a[1]), "r"(a[2]), "r"(a[3]), "r"(b0), "r"(b1));
}
__device__ __forceinline__ void split2(float x, __nv_bfloat16& h, __nv_bfloat16& l) {
    h = __float2bfloat16(x);
    l = __float2bfloat16(x - __bfloat162float(h));
}
__device__ __forceinline__ uint32_t pack2(__nv_bfloat16 a, __nv_bfloat16 b) {
    return (uint32_t)__bfloat16_as_ushort(a) | ((uint32_t)__bfloat16_as_ushort(b) << 16);
}

// ---------------- mask build (dtype-agnostic) ----------------
__global__ void build_block_mask(const unsigned char* __restrict__ m)
{
    const unsigned char b1 = m[1];
    int esz = (b1 == 0) ? 4 : (b1 == 1 ? 1 : 2);
    int idx = blockIdx.x * blockDim.x + threadIdx.x;
    if (idx >= NBLK * NBLK) return;
    int qb = idx / NBLK, kb = idx % NBLK;
    size_t elem = (size_t)(qb * BS) * SEQ + (size_t)kb * BS;
    bool allowed;
    if (esz == 1)      allowed = m[elem] != 0;
    else if (esz == 2) allowed = ((const unsigned short*)m)[elem] != 0;
    else               allowed = ((const unsigned int*)m)[elem] != 0;
    g_bm[idx] = allowed ? 1 : 0;
}

// ---------------- fp32 -> bf16 split conversions (GEMM operands) ----------------
__global__ void conv_act(const float* __restrict__ X, __nv_bfloat16* __restrict__ out, int rows)
{
    int i = blockIdx.x * blockDim.x + threadIdx.x;
    if (i >= rows * DIM) return;
    int r = i >> 10, c = i & 1023;
    __nv_bfloat16 h, l; split2(X[i], h, l);
    size_t base = (size_t)r * KTOT;
    out[base + c] = h; out[base + 1024 + c] = h; out[base + 2048 + c] = l;
}
__global__ void conv_wgt(const float* __restrict__ W, __nv_bfloat16* __restrict__ out)
{
    int i = blockIdx.x * blockDim.x + threadIdx.x;
    if (i >= DIM * DIM) return;
    int r = i >> 10, c = i & 1023;
    __nv_bfloat16 h, l; split2(W[i], h, l);
    size_t base = (size_t)r * KTOT;
    out[base + c] = h; out[base + 1024 + c] = l; out[base + 2048 + c] = h;
}

// ---------------- attention operand conversions ----------------
// Q/K: [B*SEQ, DIM] -> per (b,h): [SEQ, 192] ; Q=[hi|hi|lo], K=[hi|lo|hi]
__global__ void conv_qk(const float* __restrict__ Q, const float* __restrict__ K,
                        __nv_bfloat16* __restrict__ Qa, __nv_bfloat16* __restrict__ Ka)
{
    int i = blockIdx.x * blockDim.x + threadIdx.x;
    if (i >= MROWS * DIM) return;
    int tl = i >> 10, c = i & 1023;
    int h = c >> 6, d = c & 63;
    int b = tl >> 11, t = tl & 2047;
    size_t base = ((size_t)(b * NH + h) * SEQ + t) * 192;
    __nv_bfloat16 hh, ll;
    split2(Q[i], hh, ll);
    Qa[base + d] = hh; Qa[base + 64 + d] = hh; Qa[base + 128 + d] = ll;
    split2(K[i], hh, ll);
    Ka[base + d] = hh; Ka[base + 64 + d] = ll; Ka[base + 128 + d] = hh;
}
// V: transpose per (b,h,kb) tile -> Vt[d, 192] = [hi|lo|hi] over j
__global__ void conv_vt(const float* __restrict__ V, __nv_bfloat16* __restrict__ Va)
{
    __shared__ float tile[64][65];
    int bid = blockIdx.x;            // (b*NH+h)*NBLK + kb
    int kb = bid & 31, bh = bid >> 5;
    int b = bh >> 4, h = bh & 15;
    int tid = threadIdx.x;
    for (int i = tid; i < 4096; i += 128) {
        int t = i >> 6, d = i & 63;
        tile[t][d] = V[((size_t)(b * SEQ + kb * 64 + t)) * DIM + h * 64 + d];
    }
    __syncthreads();
    for (int i = tid; i < 4096; i += 128) {
        int d = i >> 6, j = i & 63;
        __nv_bfloat16 hh, ll; split2(tile[j][d], hh, ll);
        size_t base = ((size_t)bid * 64 + d) * 192;
        Va[base + j] = hh; Va[base + 64 + j] = ll; Va[base + 128 + j] = hh;
    }
}

// ---------------- mma.sync GEMM (unchanged from round 4) ----------------
__global__ void __launch_bounds__(256, 1)
gemm_mma(const __nv_bfloat16* __restrict__ A, const __nv_bfloat16* __restrict__ Bw,
         float* __restrict__ C)
{
    extern __shared__ char dsm[];
    const uint32_t sb = smem_u32(dsm);
    const int tid = threadIdx.x;
    const int wid = tid >> 5, l = tid & 31;
    const int wm = wid >> 2, wn = wid & 3;
    const int m0 = blockIdx.y * TM, n0 = blockIdx.x * TN;

    const int r = tid >> 1;
    const int cb = (tid & 1) * 4;
    const __nv_bfloat16* Ag = A + (size_t)(m0 + r) * KTOT;
    const __nv_bfloat16* Bg = Bw + (size_t)(n0 + r) * KTOT;
    char* sA = dsm;
    char* sB = dsm + 2 * STAGE_BYTES;

    float acc[4][4][4];
#pragma unroll
    for (int i = 0; i < 4; i++)
#pragma unroll
        for (int j = 0; j < 4; j++)
#pragma unroll
            for (int q = 0; q < 4; q++) acc[i][j][q] = 0.f;

    const uint32_t a_off = (uint32_t)((l & 15) * RSB + (l >> 4) * 16);
    const uint32_t b_off = (uint32_t)(((l & 7) + ((l >> 4) & 1) * 8) * RSB + ((l >> 3) & 1) * 16);

    uint4 sa[4], sbv[4];
#pragma unroll
    for (int q = 0; q < 4; q++) {
        sa[q]  = *(const uint4*)(Ag + (cb + q) * 8);
        sbv[q] = *(const uint4*)(Bg + (cb + q) * 8);
    }
#pragma unroll
    for (int q = 0; q < 4; q++) {
        *(uint4*)(sA + r * RSB + (cb + q) * 16) = sa[q];
        *(uint4*)(sB + r * RSB + (cb + q) * 16) = sbv[q];
    }
    __syncthreads();

    for (int i = 0; i < NCHUNK; i++) {
        if (i + 1 < NCHUNK) {
            const int k0 = (i + 1) * KCH;
#pragma unroll
            for (int q = 0; q < 4; q++) {
                sa[q]  = *(const uint4*)(Ag + k0 + (cb + q) * 8);
                sbv[q] = *(const uint4*)(Bg + k0 + (cb + q) * 8);
            }
        }
        const uint32_t abase = sb + (i & 1) * STAGE_BYTES + (uint32_t)(wm * 64) * RSB + a_off;
        const uint32_t bbase = sb + 2 * STAGE_BYTES + (i & 1) * STAGE_BYTES
                               + (uint32_t)(wn * 32) * RSB + b_off;
#pragma unroll
        for (int ks = 0; ks < 4; ks++) {
            uint32_t af[4][4], bf[2][4];
#pragma unroll
            for (int mt = 0; mt < 4; mt++)
                LDSM_X4(af[mt][0], af[mt][1], af[mt][2], af[mt][3],
                        abase + mt * (16 * RSB) + ks * 32);
#pragma unroll
            for (int g = 0; g < 2; g++)
                LDSM_X4(bf[g][0], bf[g][1], bf[g][2], bf[g][3],
                        bbase + g * (16 * RSB) + ks * 32);
#pragma unroll
            for (int mt = 0; mt < 4; mt++)
#pragma unroll
                for (int nt = 0; nt < 4; nt++)
                    mma16816(acc[mt][nt], af[mt], bf[nt >> 1][(nt & 1) * 2],
                             bf[nt >> 1][(nt & 1) * 2 + 1]);
        }
        if (i + 1 < NCHUNK) {
            const int s = (i + 1) & 1;
#pragma unroll
            for (int q = 0; q < 4; q++) {
                *(uint4*)(sA + s * STAGE_BYTES + r * RSB + (cb + q) * 16) = sa[q];
                *(uint4*)(sB + s * STAGE_BYTES + r * RSB + (cb + q) * 16) = sbv[q];
            }
        }
        __syncthreads();
    }
#pragma unroll
    for (int mt = 0; mt < 4; mt++) {
#pragma unroll
        for (int nt = 0; nt < 4; nt++) {
            const int mr = m0 + wm * 64 + mt * 16 + (l >> 2);
            const int nc = n0 + wn * 32 + nt * 8 + (l & 3) * 2;
            *(float2*)(C + (size_t)mr * DIM + nc) =
                make_float2(acc[mt][nt][0], acc[mt][nt][1]);
            *(float2*)(C + (size_t)(mr + 8) * DIM + nc) =
                make_float2(acc[mt][nt][2], acc[mt][nt][3]);
        }
    }
}

// ---------------- tensor-core block-sparse flash attention ----------------
// CTA = (qb, h, b). 4 warps; warp w owns query rows [w*16, w*16+16).
// K-dim = 192 (3-term split). S = Qa·Ka^T (K-major both), O += P·Vt^T.
__global__ void __launch_bounds__(128, 1)
attn_mma(const __nv_bfloat16* __restrict__ Qa, const __nv_bfloat16* __restrict__ Ka,
         const __nv_bfloat16* __restrict__ Va, float* __restrict__ O)
{
    extern __shared__ char sm[];
    const uint32_t sb = smem_u32(sm);
    char* sQ  = sm;
    char* sK  = sm + ATILE;
    char* sVt = sm + 2 * ATILE;
    char* sP  = sm + 3 * ATILE;

    const int tid = threadIdx.x, wid = tid >> 5, l = tid & 31;
    const int qb = blockIdx.x, h = blockIdx.y, b = blockIdx.z;
    const size_t bh = (size_t)(b * NH + h);

    // load Q tile (64 rows x 384B contiguous)
    const uint4* Qg = (const uint4*)(Qa + (bh * SEQ + qb * 64) * 192);
    for (int i = tid; i < 1536; i += 128) {
        int rr = i / 24, cc = i % 24;
        *(uint4*)(sQ + rr * ARS + cc * 16) = Qg[i];
    }

    float o[8][4];
#pragma unroll
    for (int nt = 0; nt < 8; nt++)
#pragma unroll
        for (int q = 0; q < 4; q++) o[nt][q] = 0.f;
    float m0 = -INFINITY, m1 = -INFINITY, l0 = 0.f, l1 = 0.f;

    const uint32_t a_off = (uint32_t)((l & 15) * ARS + (l >> 4) * 16);
    const uint32_t b_off = (uint32_t)(((l & 7) + ((l >> 4) & 1) * 8) * ARS + ((l >> 3) & 1) * 16);
    const uint32_t aQ = sb + (uint32_t)(wid * 16) * ARS + a_off;
    const uint32_t bK = sb + ATILE + b_off;
    const uint32_t bV = sb + 2 * ATILE + b_off;
    const uint32_t aP = sb + 3 * ATILE + (uint32_t)(wid * 16) * ARS + a_off;
    char* sPw = sP + (size_t)(wid * 16) * ARS;   // this warp's P rows
    const float scale = 0.125f;

    for (int kb = 0; kb < NBLK; kb++) {
        if (!g_bm[qb * NBLK + kb]) continue;
        __syncthreads();                          // sK/sVt reusable
        const uint4* Kg = (const uint4*)(Ka + (bh * SEQ + kb * 64) * 192);
        const uint4* Vg = (const uint4*)(Va + ((bh * NBLK + kb) * 64) * 192);
        for (int i = tid; i < 1536; i += 128) {
            int rr = i / 24, cc = i % 24;
            *(uint4*)(sK + rr * ARS + cc * 16)  = Kg[i];
            *(uint4*)(sVt + rr * ARS + cc * 16) = Vg[i];
        }
        __syncthreads();

        // ---- S = Q K^T (warp rows x 64 keys), K=192 ----
        float s[8][4];
#pragma unroll
        for (int nt = 0; nt < 8; nt++)
#pragma unroll
            for (int q = 0; q < 4; q++) s[nt][q] = 0.f;
#pragma unroll
        for (int ks = 0; ks < 12; ks++) {
            uint32_t af[4], bf[4][4];
            LDSM_X4(af[0], af[1], af[2], af[3], aQ + ks * 32);
#pragma unroll
            for (int g = 0; g < 4; g++)
                LDSM_X4(bf[g][0], bf[g][1], bf[g][2], bf[g][3],
                        bK + g * (16 * ARS) + ks * 32);
#pragma unroll
            for (int nt = 0; nt < 8; nt++)
                mma16816(s[nt], af, bf[nt >> 1][(nt & 1) * 2], bf[nt >> 1][(nt & 1) * 2 + 1]);
        }

        // ---- online softmax + P split into smem ----
        float vm0 = -INFINITY, vm1 = -INFINITY;
#pragma unroll
        for (int nt = 0; nt < 8; nt++) {
#pragma unroll
            for (int q = 0; q < 4; q++) s[nt][q] *= scale;
            vm0 = fmaxf(vm0, fmaxf(s[nt][0], s[nt][1]));
            vm1 = fmaxf(vm1, fmaxf(s[nt][2], s[nt][3]));
        }
        vm0 = fmaxf(vm0, __shfl_xor_sync(0xffffffff, vm0, 1));
        vm0 = fmaxf(vm0, __shfl_xor_sync(0xffffffff, vm0, 2));
        vm1 = fmaxf(vm1, __shfl_xor_sync(0xffffffff, vm1, 1));
        vm1 = fmaxf(vm1, __shfl_xor_sync(0xffffffff, vm1, 2));

        const float mn0 = fmaxf(m0, vm0), mn1 = fmaxf(m1, vm1);
        const float al0 = __expf(m0 - mn0), al1 = __expf(m1 - mn1);
        m0 = mn0; m1 = mn1;

        const int pr0 = (l >> 2), pc = (l & 3) * 2;
        float rs0 = 0.f, rs1 = 0.f;
#pragma unroll
        for (int nt = 0; nt < 8; nt++) {
            float p00 = __expf(s[nt][0] - mn0), p01 = __expf(s[nt][1] - mn0);
            float p10 = __expf(s[nt][2] - mn1), p11 = __expf(s[nt][3] - mn1);
            rs0 += p00 + p01; rs1 += p10 + p11;
            __nv_bfloat16 h00, l00, h01, l01, h10, l10, h11, l11;
            split2(p00, h00, l00); split2(p01, h01, l01);
            split2(p10, h10, l10); split2(p11, h11, l11);
            uint32_t hi0 = pack2(h00, h01), lo0 = pack2(l00, l01);
            uint32_t hi1 = pack2(h10, h11), lo1 = pack2(l10, l11);
            const int c = nt * 8 + pc;
            char* row0 = sPw + pr0 * ARS;
            char* row1 = sPw + (pr0 + 8) * ARS;
            *(uint32_t*)(row0 + c * 2)         = hi0;
            *(uint32_t*)(row0 + (64 + c) * 2)  = hi0;
            *(uint32_t*)(row0 + (128 + c) * 2) = lo0;
            *(uint32_t*)(row1 + c * 2)         = hi1;
            *(uint32_t*)(row1 + (64 + c) * 2)  = hi1;
            *(uint32_t*)(row1 + (128 + c) * 2) = lo1;
            o[nt][0] *= al0; o[nt][1] *= al0;
            o[nt][2] *= al1; o[nt][3] *= al1;
        }
        rs0 += __shfl_xor_sync(0xffffffff, rs0, 1);
        rs0 += __shfl_xor_sync(0xffffffff, rs0, 2);
        rs1 += __shfl_xor_sync(0xffffffff, rs1, 1);
        rs1 += __shfl_xor_sync(0xffffffff, rs1, 2);
        l0 = l0 * al0 + rs0;
        l1 = l1 * al1 + rs1;
        __syncwarp();

        // ---- O += P Vt^T ----
#pragma unroll
        for (int ks = 0; ks < 12; ks++) {
            uint32_t af[4], bf[4][4];
            LDSM_X4(af[0], af[1], af[2], af[3], aP + ks * 32);
#pragma unroll
            for (int g = 0; g < 4; g++)
                LDSM_X4(bf[g][0], bf[g][1], bf[g][2], bf[g][3],
                        bV + g * (16 * ARS) + ks * 32);
#pragma unroll
            for (int nt = 0; nt < 8; nt++)
                mma16816(o[nt], af, bf[nt >> 1][(nt & 1) * 2], bf[nt >> 1][(nt & 1) * 2 + 1]);
        }
    }

    // epilogue
    const float inv0 = 1.f / l0, inv1 = 1.f / l1;
    const int r0 = qb * 64 + wid * 16 + (l >> 2);
    const int c0 = h * 64 + (l & 3) * 2;
#pragma unroll
    for (int nt = 0; nt < 8; nt++) {
        *(float2*)(O + ((size_t)(b * SEQ + r0)) * DIM + c0 + nt * 8) =
            make_float2(o[nt][0] * inv0, o[nt][1] * inv0);
        *(float2*)(O + ((size_t)(b * SEQ + r0 + 8)) * DIM + c0 + nt * 8) =
            make_float2(o[nt][2] * inv1, o[nt][3] * inv1);
    }
}

// ---------------- launcher ----------------
extern "C" void kernel_launch(void* const* d_in, const int* in_sizes, int n_in,
                              void* d_out, int out_size)
{
    const float* X  = (const float*)d_in[0];
    const float* Wq = (const float*)d_in[1];
    const float* Wk = (const float*)d_in[2];
    const float* Wv = (const float*)d_in[3];
    const float* Wo = (const float*)d_in[4];
    const unsigned char* mask = (const unsigned char*)d_in[5];
    float* out = (float*)d_out;

    float *Qb, *Kb, *Vb, *Ob;
    __nv_bfloat16 *Xc, *Oc, *Wc, *Qa, *Ka, *Va;
    cudaGetSymbolAddress((void**)&Qb, g_Q);
    cudaGetSymbolAddress((void**)&Kb, g_K);
    cudaGetSymbolAddress((void**)&Vb, g_V);
    cudaGetSymbolAddress((void**)&Ob, g_O);
    cudaGetSymbolAddress((void**)&Xc, g_Xc);
    cudaGetSymbolAddress((void**)&Oc, g_Oc);
    cudaGetSymbolAddress((void**)&Wc, g_Wc);
    cudaGetSymbolAddress((void**)&Qa, g_Qa);
    cudaGetSymbolAddress((void**)&Ka, g_Ka);
    cudaGetSymbolAddress((void**)&Va, g_Va);

    cudaFuncSetAttribute(gemm_mma, cudaFuncAttributeMaxDynamicSharedMemorySize, SM_TOTAL);
    cudaFuncSetAttribute(attn_mma, cudaFuncAttributeMaxDynamicSharedMemorySize, ASM_TOTAL);

    build_block_mask<<<1, 1024>>>(mask);

    conv_act<<<(MROWS * DIM + 255) / 256, 256>>>(X, Xc, MROWS);
    conv_wgt<<<(DIM * DIM + 255) / 256, 256>>>(Wq, Wc + 0 * (size_t)DIM * KTOT);
    conv_wgt<<<(DIM * DIM + 255) / 256, 256>>>(Wk, Wc + 1 * (size_t)DIM * KTOT);
    conv_wgt<<<(DIM * DIM + 255) / 256, 256>>>(Wv, Wc + 2 * (size_t)DIM * KTOT);
    conv_wgt<<<(DIM * DIM + 255) / 256, 256>>>(Wo, Wc + 3 * (size_t)DIM * KTOT);

    dim3 ggrid(DIM / TN, MROWS / TM);   // (8, 32)
    gemm_mma<<<ggrid, 256, SM_TOTAL>>>(Xc, Wc + 0 * (size_t)DIM * KTOT, Qb);
    gemm_mma<<<ggrid, 256, SM_TOTAL>>>(Xc, Wc + 1 * (size_t)DIM * KTOT, Kb);
    gemm_mma<<<ggrid, 256, SM_TOTAL>>>(Xc, Wc + 2 * (size_t)DIM * KTOT, Vb);

    conv_qk<<<(MROWS * DIM + 255) / 256, 256>>>(Qb, Kb, Qa, Ka);
    conv_vt<<<BATCH * NH * NBLK, 128>>>(Vb, Va);

    dim3 agrid(NBLK, NH, BATCH);        // (32, 16, 2)
    attn_mma<<<agrid, 128, ASM_TOTAL>>>(Qa, Ka, Va, Ob);

    conv_act<<<(MROWS * DIM + 255) / 256, 256>>>(Ob, Oc, MROWS);
    gemm_mma<<<ggrid, 256, SM_TOTAL>>>(Oc, Wc + 3 * (size_t)DIM * KTOT, out);
}

// round 6
// speedup vs baseline: 2.6573x; 1.0555x over previous
#include <cuda_runtime.h>
#include <cuda_bf16.h>
#include <math.h>
#include <stdint.h>

#define BATCH 2
#define SEQ   2048
#define DIM   1024
#define NH    16
#define HD    64
#define NBLK  32
#define BS    64
#define MROWS (BATCH * SEQ)        // 4096
#define KTOT  3072                 // 3 x 1024 (hi|hi|lo split-K)
#define KCH   64
#define NCHUNK (KTOT / KCH)        // 48
#define TM    128
#define TN    128
#define RSB   144                  // GEMM smem row stride bytes
#define STAGE 18432                // 128 rows * 144B, one operand one stage
#define NSTG  3
#define SM_TOTAL (2 * NSTG * STAGE)   // 110592

// attention smem: 4 tiles of 64 rows x 192 bf16, row stride 400B
#define ARS   400
#define ATILE (64 * ARS)
#define ASM_TOTAL (4 * ATILE)      // 102400

// ---------------- device scratch ----------------
__device__ float g_V[MROWS * DIM];
__device__ __nv_bfloat16 g_Xc[(size_t)MROWS * KTOT];
__device__ __nv_bfloat16 g_Oc[(size_t)MROWS * KTOT];
__device__ __nv_bfloat16 g_Wc[4][(size_t)DIM * KTOT];
__device__ __nv_bfloat16 g_Qa[(size_t)BATCH * NH * SEQ * 192];   // [hi|hi|lo]
__device__ __nv_bfloat16 g_Ka[(size_t)BATCH * NH * SEQ * 192];   // [hi|lo|hi]
__device__ __nv_bfloat16 g_Va[(size_t)BATCH * NH * NBLK * 64 * 192];
__device__ unsigned char g_bm[NBLK * NBLK];

// ---------------- helpers ----------------
__device__ __forceinline__ uint32_t smem_u32(const void* p) {
    uint32_t a;
    asm("{ .reg .u64 t; cvta.to.shared.u64 t, %1; cvt.u32.u64 %0, t; }" : "=r"(a) : "l"(p));
    return a;
}
#define LDSM_X4(r0, r1, r2, r3, addr) \
    asm volatile("ldmatrix.sync.aligned.m8n8.x4.shared.b16 {%0,%1,%2,%3}, [%4];" \
        : "=r"(r0), "=r"(r1), "=r"(r2), "=r"(r3) : "r"(addr))
#define CP16(saddr, gptr) \
    asm volatile("cp.async.cg.shared.global [%0], [%1], 16;" :: "r"(saddr), "l"(gptr))
#define CP_COMMIT() asm volatile("cp.async.commit_group;" ::: "memory")
#define CP_WAIT(n)  asm volatile("cp.async.wait_group %0;" :: "n"(n) : "memory")

__device__ __forceinline__ void mma16816(float* c, const uint32_t* a, uint32_t b0, uint32_t b1) {
    asm volatile("mma.sync.aligned.m16n8k16.row.col.f32.bf16.bf16.f32 "
        "{%0,%1,%2,%3}, {%4,%5,%6,%7}, {%8,%9}, {%0,%1,%2,%3};"
        : "+f"(c[0]), "+f"(c[1]), "+f"(c[2]), "+f"(c[3])
        : "r"(a[0]), "r"(a[1]), "r"(a[2]), "r"(a[3]), "r"(b0), "r"(b1));
}
__device__ __forceinline__ void split2(float x, __nv_bfloat16& h, __nv_bfloat16& l) {
    h = __float2bfloat16(x);
    l = __float2bfloat16(x - __bfloat162float(h));
}
__device__ __forceinline__ uint32_t pack2(__nv_bfloat16 a, __nv_bfloat16 b) {
    return (uint32_t)__bfloat16_as_ushort(a) | ((uint32_t)__bfloat16_as_ushort(b) << 16);
}

// ---------------- mask build (dtype-agnostic) ----------------
__global__ void build_block_mask(const unsigned char* __restrict__ m)
{
    const unsigned char b1 = m[1];
    int esz = (b1 == 0) ? 4 : (b1 == 1 ? 1 : 2);
    int idx = blockIdx.x * blockDim.x + threadIdx.x;
    if (idx >= NBLK * NBLK) return;
    int qb = idx / NBLK, kb = idx % NBLK;
    size_t elem = (size_t)(qb * BS) * SEQ + (size_t)kb * BS;
    bool allowed;
    if (esz == 1)      allowed = m[elem] != 0;
    else if (esz == 2) allowed = ((const unsigned short*)m)[elem] != 0;
    else               allowed = ((const unsigned int*)m)[elem] != 0;
    g_bm[idx] = allowed ? 1 : 0;
}

// ---------------- fp32 -> bf16 split conversions ----------------
__global__ void conv_act(const float* __restrict__ X, __nv_bfloat16* __restrict__ out, int rows)
{
    int i = blockIdx.x * blockDim.x + threadIdx.x;
    if (i >= rows * DIM) return;
    int r = i >> 10, c = i & 1023;
    __nv_bfloat16 h, l; split2(X[i], h, l);
    size_t base = (size_t)r * KTOT;
    out[base + c] = h; out[base + 1024 + c] = h; out[base + 2048 + c] = l;
}
__global__ void conv_wgt(const float* __restrict__ W, __nv_bfloat16* __restrict__ out)
{
    int i = blockIdx.x * blockDim.x + threadIdx.x;
    if (i >= DIM * DIM) return;
    int r = i >> 10, c = i & 1023;
    __nv_bfloat16 h, l; split2(W[i], h, l);
    size_t base = (size_t)r * KTOT;
    out[base + c] = h; out[base + 1024 + c] = l; out[base + 2048 + c] = h;
}
// V transpose per (b,h,kb): Vt[d, 192j] = [hi|lo|hi]
__global__ void conv_vt(const float* __restrict__ V, __nv_bfloat16* __restrict__ Va)
{
    __shared__ float tile[64][65];
    int bid = blockIdx.x;
    int kb = bid & 31, bh = bid >> 5;
    int b = bh >> 4, h = bh & 15;
    int tid = threadIdx.x;
    for (int i = tid; i < 4096; i += 128) {
        int t = i >> 6, d = i & 63;
        tile[t][d] = V[((size_t)(b * SEQ + kb * 64 + t)) * DIM + h * 64 + d];
    }
    __syncthreads();
    for (int i = tid; i < 4096; i += 128) {
        int d = i >> 6, j = i & 63;
        __nv_bfloat16 hh, ll; split2(tile[j][d], hh, ll);
        size_t base = ((size_t)bid * 64 + d) * 192;
        Va[base + j] = hh; Va[base + 64 + j] = ll; Va[base + 128 + j] = hh;
    }
}

// ---------------- pipelined mma.sync GEMM ----------------
// MODE 0: C fp32 [MROWS, DIM].  MODE 1: Qa split [hi|hi|lo] per-head.
// MODE 2: Ka split [hi|lo|hi] per-head.
template<int MODE>
__global__ void __launch_bounds__(256, 2)
gemm_mma(const __nv_bfloat16* __restrict__ A, const __nv_bfloat16* __restrict__ Bw,
         float* __restrict__ C, __nv_bfloat16* __restrict__ Cs)
{
    extern __shared__ char dsm[];
    const uint32_t sb = smem_u32(dsm);
    const int tid = threadIdx.x;
    const int wid = tid >> 5, l = tid & 31;
    const int wm = wid >> 2, wn = wid & 3;
    const int m0 = blockIdx.y * TM, n0 = blockIdx.x * TN;

    const int r = tid >> 1;
    const int cbB = (tid & 1) * 64;                 // byte offset of this thread's 64B half
    const int cbE = (tid & 1) * 32;                 // element offset
    const __nv_bfloat16* Ag = A + (size_t)(m0 + r) * KTOT + cbE;
    const __nv_bfloat16* Bg = Bw + (size_t)(n0 + r) * KTOT + cbE;
    const uint32_t sa_row = sb + r * RSB + cbB;               // + stage*STAGE
    const uint32_t sb_row = sb + NSTG * STAGE + r * RSB + cbB;

    float acc[4][4][4];
#pragma unroll
    for (int i = 0; i < 4; i++)
#pragma unroll
        for (int j = 0; j < 4; j++)
#pragma unroll
            for (int q = 0; q < 4; q++) acc[i][j][q] = 0.f;

    const uint32_t a_off = (uint32_t)((l & 15) * RSB + (l >> 4) * 16);
    const uint32_t b_off = (uint32_t)(((l & 7) + ((l >> 4) & 1) * 8) * RSB + ((l >> 3) & 1) * 16);

    // prologue: stages 0,1
#pragma unroll
    for (int s = 0; s < NSTG - 1; s++) {
#pragma unroll
        for (int q = 0; q < 4; q++) {
            CP16(sa_row + s * STAGE + q * 16, Ag + s * KCH + q * 8);
            CP16(sb_row + s * STAGE + q * 16, Bg + s * KCH + q * 8);
        }
        CP_COMMIT();
    }

    for (int i = 0; i < NCHUNK; i++) {
        if (i < NCHUNK - 1) CP_WAIT(1); else CP_WAIT(0);
        __syncthreads();

        if (i + NSTG - 1 < NCHUNK) {
            const int s = (i + NSTG - 1) % NSTG;
            const int k0 = (i + NSTG - 1) * KCH;
#pragma unroll
            for (int q = 0; q < 4; q++) {
                CP16(sa_row + s * STAGE + q * 16, Ag + k0 + q * 8);
                CP16(sb_row + s * STAGE + q * 16, Bg + k0 + q * 8);
            }
        }
        CP_COMMIT();

        const int slot = i % NSTG;
        const uint32_t abase = sb + slot * STAGE + (uint32_t)(wm * 64) * RSB + a_off;
        const uint32_t bbase = sb + NSTG * STAGE + slot * STAGE + (uint32_t)(wn * 32) * RSB + b_off;
#pragma unroll
        for (int ks = 0; ks < 4; ks++) {
            uint32_t af[4][4], bf[2][4];
#pragma unroll
            for (int mt = 0; mt < 4; mt++)
                LDSM_X4(af[mt][0], af[mt][1], af[mt][2], af[mt][3],
                        abase + mt * (16 * RSB) + ks * 32);
#pragma unroll
            for (int g = 0; g < 2; g++)
                LDSM_X4(bf[g][0], bf[g][1], bf[g][2], bf[g][3],
                        bbase + g * (16 * RSB) + ks * 32);
#pragma unroll
            for (int mt = 0; mt < 4; mt++)
#pragma unroll
                for (int nt = 0; nt < 4; nt++)
                    mma16816(acc[mt][nt], af[mt], bf[nt >> 1][(nt & 1) * 2],
                             bf[nt >> 1][(nt & 1) * 2 + 1]);
        }
    }

    // epilogue
#pragma unroll
    for (int mt = 0; mt < 4; mt++) {
#pragma unroll
        for (int nt = 0; nt < 4; nt++) {
            const int mr = m0 + wm * 64 + mt * 16 + (l >> 2);
            const int nc = n0 + wn * 32 + nt * 8 + (l & 3) * 2;
            if (MODE == 0) {
                *(float2*)(C + (size_t)mr * DIM + nc) =
                    make_float2(acc[mt][nt][0], acc[mt][nt][1]);
                *(float2*)(C + (size_t)(mr + 8) * DIM + nc) =
                    make_float2(acc[mt][nt][2], acc[mt][nt][3]);
            } else {
                const int hh = nc >> 6, d = nc & 63;
#pragma unroll
                for (int rr = 0; rr < 2; rr++) {
                    const int row = mr + rr * 8;
                    const int bb = row >> 11, t = row & 2047;
                    const size_t base = ((size_t)(bb * NH + hh) * SEQ + t) * 192;
                    __nv_bfloat16 hx, lx, hy, ly;
                    split2(acc[mt][nt][rr * 2 + 0], hx, lx);
                    split2(acc[mt][nt][rr * 2 + 1], hy, ly);
                    const uint32_t hi = pack2(hx, hy), lo = pack2(lx, ly);
                    *(uint32_t*)(Cs + base + d) = hi;
                    if (MODE == 1) {       // Qa: [hi|hi|lo]
                        *(uint32_t*)(Cs + base + 64 + d)  = hi;
                        *(uint32_t*)(Cs + base + 128 + d) = lo;
                    } else {               // Ka: [hi|lo|hi]
                        *(uint32_t*)(Cs + base + 64 + d)  = lo;
                        *(uint32_t*)(Cs + base + 128 + d) = hi;
                    }
                }
            }
        }
    }
}

// ---------------- tensor-core block-sparse flash attention ----------------
// epilogue writes split Oc [MROWS, 3072] = [hi|hi|lo] directly.
__global__ void __launch_bounds__(128, 1)
attn_mma(const __nv_bfloat16* __restrict__ Qa, const __nv_bfloat16* __restrict__ Ka,
         const __nv_bfloat16* __restrict__ Va, __nv_bfloat16* __restrict__ Oc)
{
    extern __shared__ char sm[];
    const uint32_t sb = smem_u32(sm);
    char* sQ  = sm;
    char* sK  = sm + ATILE;
    char* sVt = sm + 2 * ATILE;
    char* sP  = sm + 3 * ATILE;

    const int tid = threadIdx.x, wid = tid >> 5, l = tid & 31;
    const int qb = blockIdx.x, h = blockIdx.y, b = blockIdx.z;
    const size_t bh = (size_t)(b * NH + h);

    const uint4* Qg = (const uint4*)(Qa + (bh * SEQ + qb * 64) * 192);
    for (int i = tid; i < 1536; i += 128) {
        int rr = i / 24, cc = i % 24;
        *(uint4*)(sQ + rr * ARS + cc * 16) = Qg[i];
    }

    float o[8][4];
#pragma unroll
    for (int nt = 0; nt < 8; nt++)
#pragma unroll
        for (int q = 0; q < 4; q++) o[nt][q] = 0.f;
    float m0 = -INFINITY, m1 = -INFINITY, l0 = 0.f, l1 = 0.f;

    const uint32_t a_off = (uint32_t)((l & 15) * ARS + (l >> 4) * 16);
    const uint32_t b_off = (uint32_t)(((l & 7) + ((l >> 4) & 1) * 8) * ARS + ((l >> 3) & 1) * 16);
    const uint32_t aQ = sb + (uint32_t)(wid * 16) * ARS + a_off;
    const uint32_t bK = sb + ATILE + b_off;
    const uint32_t bV = sb + 2 * ATILE + b_off;
    const uint32_t aP = sb + 3 * ATILE + (uint32_t)(wid * 16) * ARS + a_off;
    char* sPw = sP + (size_t)(wid * 16) * ARS;
    const float scale = 0.125f;

    for (int kb = 0; kb < NBLK; kb++) {
        if (!g_bm[qb * NBLK + kb]) continue;
        __syncthreads();
        const uint4* Kg = (const uint4*)(Ka + (bh * SEQ + kb * 64) * 192);
        const uint4* Vg = (const uint4*)(Va + ((bh * NBLK + kb) * 64) * 192);
        for (int i = tid; i < 1536; i += 128) {
            int rr = i / 24, cc = i % 24;
            *(uint4*)(sK + rr * ARS + cc * 16)  = Kg[i];
            *(uint4*)(sVt + rr * ARS + cc * 16) = Vg[i];
        }
        __syncthreads();

        float s[8][4];
#pragma unroll
        for (int nt = 0; nt < 8; nt++)
#pragma unroll
            for (int q = 0; q < 4; q++) s[nt][q] = 0.f;
#pragma unroll
        for (int ks = 0; ks < 12; ks++) {
            uint32_t af[4], bf[4][4];
            LDSM_X4(af[0], af[1], af[2], af[3], aQ + ks * 32);
#pragma unroll
            for (int g = 0; g < 4; g++)
                LDSM_X4(bf[g][0], bf[g][1], bf[g][2], bf[g][3],
                        bK + g * (16 * ARS) + ks * 32);
#pragma unroll
            for (int nt = 0; nt < 8; nt++)
                mma16816(s[nt], af, bf[nt >> 1][(nt & 1) * 2], bf[nt >> 1][(nt & 1) * 2 + 1]);
        }

        float vm0 = -INFINITY, vm1 = -INFINITY;
#pragma unroll
        for (int nt = 0; nt < 8; nt++) {
#pragma unroll
            for (int q = 0; q < 4; q++) s[nt][q] *= scale;
            vm0 = fmaxf(vm0, fmaxf(s[nt][0], s[nt][1]));
            vm1 = fmaxf(vm1, fmaxf(s[nt][2], s[nt][3]));
        }
        vm0 = fmaxf(vm0, __shfl_xor_sync(0xffffffff, vm0, 1));
        vm0 = fmaxf(vm0, __shfl_xor_sync(0xffffffff, vm0, 2));
        vm1 = fmaxf(vm1, __shfl_xor_sync(0xffffffff, vm1, 1));
        vm1 = fmaxf(vm1, __shfl_xor_sync(0xffffffff, vm1, 2));

        const float mn0 = fmaxf(m0, vm0), mn1 = fmaxf(m1, vm1);
        const float al0 = __expf(m0 - mn0), al1 = __expf(m1 - mn1);
        m0 = mn0; m1 = mn1;

        const int pr0 = (l >> 2), pc = (l & 3) * 2;
        float rs0 = 0.f, rs1 = 0.f;
#pragma unroll
        for (int nt = 0; nt < 8; nt++) {
            float p00 = __expf(s[nt][0] - mn0), p01 = __expf(s[nt][1] - mn0);
            float p10 = __expf(s[nt][2] - mn1), p11 = __expf(s[nt][3] - mn1);
            rs0 += p00 + p01; rs1 += p10 + p11;
            __nv_bfloat16 h00, l00, h01, l01, h10, l10, h11, l11;
            split2(p00, h00, l00); split2(p01, h01, l01);
            split2(p10, h10, l10); split2(p11, h11, l11);
            uint32_t hi0 = pack2(h00, h01), lo0 = pack2(l00, l01);
            uint32_t hi1 = pack2(h10, h11), lo1 = pack2(l10, l11);
            const int c = nt * 8 + pc;
            char* row0 = sPw + pr0 * ARS;
            char* row1 = sPw + (pr0 + 8) * ARS;
            *(uint32_t*)(row0 + c * 2)         = hi0;
            *(uint32_t*)(row0 + (64 + c) * 2)  = hi0;
            *(uint32_t*)(row0 + (128 + c) * 2) = lo0;
            *(uint32_t*)(row1 + c * 2)         = hi1;
            *(uint32_t*)(row1 + (64 + c) * 2)  = hi1;
            *(uint32_t*)(row1 + (128 + c) * 2) = lo1;
            o[nt][0] *= al0; o[nt][1] *= al0;
            o[nt][2] *= al1; o[nt][3] *= al1;
        }
        rs0 += __shfl_xor_sync(0xffffffff, rs0, 1);
        rs0 += __shfl_xor_sync(0xffffffff, rs0, 2);
        rs1 += __shfl_xor_sync(0xffffffff, rs1, 1);
        rs1 += __shfl_xor_sync(0xffffffff, rs1, 2);
        l0 = l0 * al0 + rs0;
        l1 = l1 * al1 + rs1;
        __syncwarp();

#pragma unroll
        for (int ks = 0; ks < 12; ks++) {
            uint32_t af[4], bf[4][4];
            LDSM_X4(af[0], af[1], af[2], af[3], aP + ks * 32);
#pragma unroll
            for (int g = 0; g < 4; g++)
                LDSM_X4(bf[g][0], bf[g][1], bf[g][2], bf[g][3],
                        bV + g * (16 * ARS) + ks * 32);
#pragma unroll
            for (int nt = 0; nt < 8; nt++)
                mma16816(o[nt], af, bf[nt >> 1][(nt & 1) * 2], bf[nt >> 1][(nt & 1) * 2 + 1]);
        }
    }

    // epilogue: write split Oc [hi|hi|lo], row = token, 3072 cols
    const float inv0 = 1.f / l0, inv1 = 1.f / l1;
    const int r0 = qb * 64 + wid * 16 + (l >> 2);
    const int c0 = h * 64 + (l & 3) * 2;
#pragma unroll
    for (int nt = 0; nt < 8; nt++) {
        const int c = c0 + nt * 8;
#pragma unroll
        for (int rr = 0; rr < 2; rr++) {
            const float inv = rr ? inv1 : inv0;
            const size_t rowb = (size_t)(b * SEQ + r0 + rr * 8) * KTOT;
            __nv_bfloat16 hx, lx, hy, ly;
            split2(o[nt][rr * 2 + 0] * inv, hx, lx);
            split2(o[nt][rr * 2 + 1] * inv, hy, ly);
            *(uint32_t*)(Oc + rowb + c)        = pack2(hx, hy);
            *(uint32_t*)(Oc + rowb + 1024 + c) = pack2(hx, hy);
            *(uint32_t*)(Oc + rowb + 2048 + c) = pack2(lx, ly);
        }
    }
}

// ---------------- launcher ----------------
extern "C" void kernel_launch(void* const* d_in, const int* in_sizes, int n_in,
                              void* d_out, int out_size)
{
    const float* X  = (const float*)d_in[0];
    const float* Wq = (const float*)d_in[1];
    const float* Wk = (const float*)d_in[2];
    const float* Wv = (const float*)d_in[3];
    const float* Wo = (const float*)d_in[4];
    const unsigned char* mask = (const unsigned char*)d_in[5];
    float* out = (float*)d_out;

    float *Vb;
    __nv_bfloat16 *Xc, *Oc, *Wc, *Qa, *Ka, *Va;
    cudaGetSymbolAddress((void**)&Vb, g_V);
    cudaGetSymbolAddress((void**)&Xc, g_Xc);
    cudaGetSymbolAddress((void**)&Oc, g_Oc);
    cudaGetSymbolAddress((void**)&Wc, g_Wc);
    cudaGetSymbolAddress((void**)&Qa, g_Qa);
    cudaGetSymbolAddress((void**)&Ka, g_Ka);
    cudaGetSymbolAddress((void**)&Va, g_Va);

    cudaFuncSetAttribute(gemm_mma<0>, cudaFuncAttributeMaxDynamicSharedMemorySize, SM_TOTAL);
    cudaFuncSetAttribute(gemm_mma<1>, cudaFuncAttributeMaxDynamicSharedMemorySize, SM_TOTAL);
    cudaFuncSetAttribute(gemm_mma<2>, cudaFuncAttributeMaxDynamicSharedMemorySize, SM_TOTAL);
    cudaFuncSetAttribute(attn_mma, cudaFuncAttributeMaxDynamicSharedMemorySize, ASM_TOTAL);

    build_block_mask<<<1, 1024>>>(mask);

    conv_act<<<(MROWS * DIM + 255) / 256, 256>>>(X, Xc, MROWS);
    conv_wgt<<<(DIM * DIM + 255) / 256, 256>>>(Wq, Wc + 0 * (size_t)DIM * KTOT);
    conv_wgt<<<(DIM * DIM + 255) / 256, 256>>>(Wk, Wc + 1 * (size_t)DIM * KTOT);
    conv_wgt<<<(DIM * DIM + 255) / 256, 256>>>(Wv, Wc + 2 * (size_t)DIM * KTOT);
    conv_wgt<<<(DIM * DIM + 255) / 256, 256>>>(Wo, Wc + 3 * (size_t)DIM * KTOT);

    dim3 ggrid(DIM / TN, MROWS / TM);   // (8, 32)
    gemm_mma<1><<<ggrid, 256, SM_TOTAL>>>(Xc, Wc + 0 * (size_t)DIM * KTOT, nullptr, Qa);
    gemm_mma<2><<<ggrid, 256, SM_TOTAL>>>(Xc, Wc + 1 * (size_t)DIM * KTOT, nullptr, Ka);
    gemm_mma<0><<<ggrid, 256, SM_TOTAL>>>(Xc, Wc + 2 * (size_t)DIM * KTOT, Vb, nullptr);

    conv_vt<<<BATCH * NH * NBLK, 128>>>(Vb, Va);

    dim3 agrid(NBLK, NH, BATCH);
    attn_mma<<<agrid, 128, ASM_TOTAL>>>(Qa, Ka, Va, Oc);

    gemm_mma<0><<<ggrid, 256, SM_TOTAL>>>(Oc, Wc + 3 * (size_t)DIM * KTOT, out, nullptr);
}

// round 7
// speedup vs baseline: 3.6286x; 1.3655x over previous
#include <cuda_runtime.h>
#include <cuda_fp16.h>
#include <math.h>
#include <stdint.h>

#define BATCH 2
#define SEQ   2048
#define DIM   1024
#define NH    16
#define HD    64
#define NBLK  32
#define BS    64
#define MROWS (BATCH * SEQ)        // 4096
#define KTOT  2048                 // 2 x 1024 fp16 split
#define KCH   64
#define NCHUNK (KTOT / KCH)        // 32
#define TM    128
#define TN    128
#define RSB   144
#define STAGE 18432
#define NSTG  3
#define SM_TOTAL (2 * NSTG * STAGE)   // 110592

// attention smem
#define ARSQ  272                  // Q/K rows: 128 fp16 = 256B + 16 pad
#define ARSV  400                  // V/P rows: 192 fp16 = 384B + 16 pad
#define QTILE (64 * ARSQ)          // 17408
#define VTILE (64 * ARSV)          // 25600
#define ASM_TOTAL (2 * QTILE + 2 * VTILE)   // 86016

// ---------------- device scratch ----------------
__device__ float  g_V[MROWS * DIM];
__device__ __half g_Xc[(size_t)MROWS * KTOT];
__device__ __half g_Oc[(size_t)MROWS * KTOT];
__device__ __half g_Wqkv[(size_t)3 * DIM * KTOT];
__device__ __half g_Wo[(size_t)DIM * KTOT];
__device__ __half g_Qa[(size_t)BATCH * NH * SEQ * 128];   // [hi|lo]
__device__ __half g_Ka[(size_t)BATCH * NH * SEQ * 128];   // [hi|hi]
__device__ __half g_Va[(size_t)BATCH * NH * NBLK * 64 * 192]; // [vhi|vlo|vhi]
__device__ unsigned char g_bm[NBLK * NBLK];

// ---------------- helpers ----------------
__device__ __forceinline__ uint32_t smem_u32(const void* p) {
    uint32_t a;
    asm("{ .reg .u64 t; cvta.to.shared.u64 t, %1; cvt.u32.u64 %0, t; }" : "=r"(a) : "l"(p));
    return a;
}
#define LDSM_X4(r0, r1, r2, r3, addr) \
    asm volatile("ldmatrix.sync.aligned.m8n8.x4.shared.b16 {%0,%1,%2,%3}, [%4];" \
        : "=r"(r0), "=r"(r1), "=r"(r2), "=r"(r3) : "r"(addr))
#define CP16(saddr, gptr) \
    asm volatile("cp.async.cg.shared.global [%0], [%1], 16;" :: "r"(saddr), "l"(gptr))
#define CP_COMMIT() asm volatile("cp.async.commit_group;" ::: "memory")
#define CP_WAIT(n)  asm volatile("cp.async.wait_group %0;" :: "n"(n) : "memory")

__device__ __forceinline__ void mma16816(float* c, const uint32_t* a, uint32_t b0, uint32_t b1) {
    asm volatile("mma.sync.aligned.m16n8k16.row.col.f32.f16.f16.f32 "
        "{%0,%1,%2,%3}, {%4,%5,%6,%7}, {%8,%9}, {%0,%1,%2,%3};"
        : "+f"(c[0]), "+f"(c[1]), "+f"(c[2]), "+f"(c[3])
        : "r"(a[0]), "r"(a[1]), "r"(a[2]), "r"(a[3]), "r"(b0), "r"(b1));
}
__device__ __forceinline__ void split2h(float x, __half& h, __half& l) {
    h = __float2half_rn(x);
    l = __float2half_rn(x - __half2float(h));
}
__device__ __forceinline__ uint32_t pack2h(__half a, __half b) {
    return (uint32_t)__half_as_ushort(a) | ((uint32_t)__half_as_ushort(b) << 16);
}

// ---------------- mask build (dtype-agnostic) ----------------
__global__ void build_block_mask(const unsigned char* __restrict__ m)
{
    const unsigned char b1 = m[1];
    int esz = (b1 == 0) ? 4 : (b1 == 1 ? 1 : 2);
    int idx = blockIdx.x * blockDim.x + threadIdx.x;
    if (idx >= NBLK * NBLK) return;
    int qb = idx / NBLK, kb = idx % NBLK;
    size_t elem = (size_t)(qb * BS) * SEQ + (size_t)kb * BS;
    bool allowed;
    if (esz == 1)      allowed = m[elem] != 0;
    else if (esz == 2) allowed = ((const unsigned short*)m)[elem] != 0;
    else               allowed = ((const unsigned int*)m)[elem] != 0;
    g_bm[idx] = allowed ? 1 : 0;
}

// ---------------- fp32 -> fp16 conversions ----------------
// activations: [rows,1024] -> [rows,2048] = [hi | lo]
__global__ void conv_act(const float* __restrict__ X, __half* __restrict__ out, int rows)
{
    int i = blockIdx.x * blockDim.x + threadIdx.x;
    if (i >= rows * DIM) return;
    int r = i >> 10, c = i & 1023;
    __half h, l; split2h(X[i], h, l);
    size_t base = (size_t)r * KTOT;
    out[base + c] = h; out[base + 1024 + c] = l;
}
// weights: [hi | hi]
__global__ void conv_wgt(const float* __restrict__ W, __half* __restrict__ out)
{
    int i = blockIdx.x * blockDim.x + threadIdx.x;
    if (i >= DIM * DIM) return;
    int r = i >> 10, c = i & 1023;
    __half h = __float2half_rn(W[i]);
    size_t base = (size_t)r * KTOT;
    out[base + c] = h; out[base + 1024 + c] = h;
}
// two weights in one launch (Wq, Wk)
__global__ void conv_wgt2(const float* __restrict__ W1, const float* __restrict__ W2,
                          __half* __restrict__ o1, __half* __restrict__ o2)
{
    int i = blockIdx.x * blockDim.x + threadIdx.x;
    if (i >= 2 * DIM * DIM) return;
    const float* W = (i < DIM * DIM) ? W1 : W2;
    __half* out = (i < DIM * DIM) ? o1 : o2;
    int j = (i < DIM * DIM) ? i : i - DIM * DIM;
    int r = j >> 10, c = j & 1023;
    __half h = __float2half_rn(W[j]);
    size_t base = (size_t)r * KTOT;
    out[base + c] = h; out[base + 1024 + c] = h;
}
// V transpose per (b,h,kb): Vt[d, 192j] = [vhi|vlo|vhi] fp16
__global__ void conv_vt(const float* __restrict__ V, __half* __restrict__ Va)
{
    __shared__ float tile[64][65];
    int bid = blockIdx.x;
    int kb = bid & 31, bh = bid >> 5;
    int b = bh >> 4, h = bh & 15;
    int tid = threadIdx.x;
    for (int i = tid; i < 4096; i += 128) {
        int t = i >> 6, d = i & 63;
        tile[t][d] = V[((size_t)(b * SEQ + kb * 64 + t)) * DIM + h * 64 + d];
    }
    __syncthreads();
    for (int i = tid; i < 4096; i += 128) {
        int d = i >> 6, j = i & 63;
        __half hh, ll; split2h(tile[j][d], hh, ll);
        size_t base = ((size_t)bid * 64 + d) * 192;
        Va[base + j] = hh; Va[base + 64 + j] = ll; Va[base + 128 + j] = hh;
    }
}

// ---------------- pipelined mma.sync GEMM ----------------
// QKV=true: B is Wqkv [3072,2048]; epilogue by column segment:
//   n<1024 -> Qa [hi|lo];  n<2048 -> Ka [hi|hi];  else -> V fp32.
// QKV=false: plain fp32 C [MROWS, DIM].
template<bool QKV>
__global__ void __launch_bounds__(256, 2)
gemm_mma(const __half* __restrict__ A, const __half* __restrict__ Bw,
         __half* __restrict__ Qa, __half* __restrict__ Ka,
         float* __restrict__ Vout, float* __restrict__ C)
{
    extern __shared__ char dsm[];
    const uint32_t sb = smem_u32(dsm);
    const int tid = threadIdx.x;
    const int wid = tid >> 5, l = tid & 31;
    const int wm = wid >> 2, wn = wid & 3;
    const int m0 = blockIdx.y * TM, n0 = blockIdx.x * TN;

    const int r = tid >> 1;
    const int cbB = (tid & 1) * 64;
    const int cbE = (tid & 1) * 32;
    const __half* Ag = A + (size_t)(m0 + r) * KTOT + cbE;
    const __half* Bg = Bw + (size_t)(n0 + r) * KTOT + cbE;
    const uint32_t sa_row = sb + r * RSB + cbB;
    const uint32_t sb_row = sb + NSTG * STAGE + r * RSB + cbB;

    float acc[4][4][4];
#pragma unroll
    for (int i = 0; i < 4; i++)
#pragma unroll
        for (int j = 0; j < 4; j++)
#pragma unroll
            for (int q = 0; q < 4; q++) acc[i][j][q] = 0.f;

    const uint32_t a_off = (uint32_t)((l & 15) * RSB + (l >> 4) * 16);
    const uint32_t b_off = (uint32_t)(((l & 7) + ((l >> 4) & 1) * 8) * RSB + ((l >> 3) & 1) * 16);

#pragma unroll
    for (int s = 0; s < NSTG - 1; s++) {
#pragma unroll
        for (int q = 0; q < 4; q++) {
            CP16(sa_row + s * STAGE + q * 16, Ag + s * KCH + q * 8);
            CP16(sb_row + s * STAGE + q * 16, Bg + s * KCH + q * 8);
        }
        CP_COMMIT();
    }

    for (int i = 0; i < NCHUNK; i++) {
        if (i < NCHUNK - 1) CP_WAIT(1); else CP_WAIT(0);
        __syncthreads();

        if (i + NSTG - 1 < NCHUNK) {
            const int s = (i + NSTG - 1) % NSTG;
            const int k0 = (i + NSTG - 1) * KCH;
#pragma unroll
            for (int q = 0; q < 4; q++) {
                CP16(sa_row + s * STAGE + q * 16, Ag + k0 + q * 8);
                CP16(sb_row + s * STAGE + q * 16, Bg + k0 + q * 8);
            }
        }
        CP_COMMIT();

        const int slot = i % NSTG;
        const uint32_t abase = sb + slot * STAGE + (uint32_t)(wm * 64) * RSB + a_off;
        const uint32_t bbase = sb + NSTG * STAGE + slot * STAGE + (uint32_t)(wn * 32) * RSB + b_off;
#pragma unroll
        for (int ks = 0; ks < 4; ks++) {
            uint32_t af[4][4], bf[2][4];
#pragma unroll
            for (int mt = 0; mt < 4; mt++)
                LDSM_X4(af[mt][0], af[mt][1], af[mt][2], af[mt][3],
                        abase + mt * (16 * RSB) + ks * 32);
#pragma unroll
            for (int g = 0; g < 2; g++)
                LDSM_X4(bf[g][0], bf[g][1], bf[g][2], bf[g][3],
                        bbase + g * (16 * RSB) + ks * 32);
#pragma unroll
            for (int mt = 0; mt < 4; mt++)
#pragma unroll
                for (int nt = 0; nt < 4; nt++)
                    mma16816(acc[mt][nt], af[mt], bf[nt >> 1][(nt & 1) * 2],
                             bf[nt >> 1][(nt & 1) * 2 + 1]);
        }
    }

    const int mode = QKV ? (n0 >> 10) : 3;   // 0=Q, 1=K, 2=V, 3=fp32 C
#pragma unroll
    for (int mt = 0; mt < 4; mt++) {
#pragma unroll
        for (int nt = 0; nt < 4; nt++) {
            const int mr = m0 + wm * 64 + mt * 16 + (l >> 2);
            const int nc = n0 + wn * 32 + nt * 8 + (l & 3) * 2;
            if (mode == 3) {
                *(float2*)(C + (size_t)mr * DIM + nc) =
                    make_float2(acc[mt][nt][0], acc[mt][nt][1]);
                *(float2*)(C + (size_t)(mr + 8) * DIM + nc) =
                    make_float2(acc[mt][nt][2], acc[mt][nt][3]);
            } else if (mode == 2) {
                const int col = nc - 2048;
                *(float2*)(Vout + (size_t)mr * DIM + col) =
                    make_float2(acc[mt][nt][0], acc[mt][nt][1]);
                *(float2*)(Vout + (size_t)(mr + 8) * DIM + col) =
                    make_float2(acc[mt][nt][2], acc[mt][nt][3]);
            } else {
                const int cl = nc & 1023;
                const int hh = cl >> 6, d = cl & 63;
                __half* dst = (mode == 0) ? Qa : Ka;
#pragma unroll
                for (int rr = 0; rr < 2; rr++) {
                    const int row = mr + rr * 8;
                    const int bb = row >> 11, t = row & 2047;
                    const size_t base = ((size_t)(bb * NH + hh) * SEQ + t) * 128;
                    __half hx, lx, hy, ly;
                    split2h(acc[mt][nt][rr * 2 + 0], hx, lx);
                    split2h(acc[mt][nt][rr * 2 + 1], hy, ly);
                    *(uint32_t*)(dst + base + d) = pack2h(hx, hy);
                    *(uint32_t*)(dst + base + 64 + d) =
                        (mode == 0) ? pack2h(lx, ly) : pack2h(hx, hy);
                }
            }
        }
    }
}

// ---------------- tensor-core block-sparse flash attention (fp16) ----------------
// QK: K=128 ([qhi|qlo] x [khi|khi]).  PV: K=192 ([Phi|Phi|Plo] x [vhi|vlo|vhi]).
__global__ void __launch_bounds__(128, 2)
attn_mma(const __half* __restrict__ Qa, const __half* __restrict__ Ka,
         const __half* __restrict__ Va, __half* __restrict__ Oc)
{
    extern __shared__ char sm[];
    const uint32_t sb = smem_u32(sm);
    char* sQ  = sm;
    char* sK  = sm + QTILE;
    char* sVt = sm + 2 * QTILE;
    char* sP  = sm + 2 * QTILE + VTILE;

    const int tid = threadIdx.x, wid = tid >> 5, l = tid & 31;
    const int qb = blockIdx.x, h = blockIdx.y, b = blockIdx.z;
    const size_t bh = (size_t)(b * NH + h);

    // Q tile: 64 rows x 256B
    const uint4* Qg = (const uint4*)(Qa + (bh * SEQ + qb * 64) * 128);
    for (int i = tid; i < 1024; i += 128) {
        int rr = i >> 4, cc = i & 15;
        *(uint4*)(sQ + rr * ARSQ + cc * 16) = Qg[i];
    }

    float o[8][4];
#pragma unroll
    for (int nt = 0; nt < 8; nt++)
#pragma unroll
        for (int q = 0; q < 4; q++) o[nt][q] = 0.f;
    float m0 = -INFINITY, m1 = -INFINITY, l0 = 0.f, l1 = 0.f;

    const uint32_t a_offQ = (uint32_t)((l & 15) * ARSQ + (l >> 4) * 16);
    const uint32_t b_offQ = (uint32_t)(((l & 7) + ((l >> 4) & 1) * 8) * ARSQ + ((l >> 3) & 1) * 16);
    const uint32_t a_offV = (uint32_t)((l & 15) * ARSV + (l >> 4) * 16);
    const uint32_t b_offV = (uint32_t)(((l & 7) + ((l >> 4) & 1) * 8) * ARSV + ((l >> 3) & 1) * 16);
    const uint32_t aQ = sb + (uint32_t)(wid * 16) * ARSQ + a_offQ;
    const uint32_t bK = sb + QTILE + b_offQ;
    const uint32_t bV = sb + 2 * QTILE + b_offV;
    const uint32_t aP = sb + 2 * QTILE + VTILE + (uint32_t)(wid * 16) * ARSV + a_offV;
    char* sPw = sP + (size_t)(wid * 16) * ARSV;
    const float scale = 0.125f;

    for (int kb = 0; kb < NBLK; kb++) {
        if (!g_bm[qb * NBLK + kb]) continue;
        __syncthreads();
        const uint4* Kg = (const uint4*)(Ka + (bh * SEQ + kb * 64) * 128);
        const uint4* Vg = (const uint4*)(Va + ((bh * NBLK + kb) * 64) * 192);
        for (int i = tid; i < 1024; i += 128) {
            int rr = i >> 4, cc = i & 15;
            *(uint4*)(sK + rr * ARSQ + cc * 16) = Kg[i];
        }
        for (int i = tid; i < 1536; i += 128) {
            int rr = i / 24, cc = i % 24;
            *(uint4*)(sVt + rr * ARSV + cc * 16) = Vg[i];
        }
        __syncthreads();

        // ---- S = Q K^T, K=128 ----
        float s[8][4];
#pragma unroll
        for (int nt = 0; nt < 8; nt++)
#pragma unroll
            for (int q = 0; q < 4; q++) s[nt][q] = 0.f;
#pragma unroll
        for (int ks = 0; ks < 8; ks++) {
            uint32_t af[4], bf[4][4];
            LDSM_X4(af[0], af[1], af[2], af[3], aQ + ks * 32);
#pragma unroll
            for (int g = 0; g < 4; g++)
                LDSM_X4(bf[g][0], bf[g][1], bf[g][2], bf[g][3],
                        bK + g * (16 * ARSQ) + ks * 32);
#pragma unroll
            for (int nt = 0; nt < 8; nt++)
                mma16816(s[nt], af, bf[nt >> 1][(nt & 1) * 2], bf[nt >> 1][(nt & 1) * 2 + 1]);
        }

        // ---- online softmax + P split into smem ----
        float vm0 = -INFINITY, vm1 = -INFINITY;
#pragma unroll
        for (int nt = 0; nt < 8; nt++) {
#pragma unroll
            for (int q = 0; q < 4; q++) s[nt][q] *= scale;
            vm0 = fmaxf(vm0, fmaxf(s[nt][0], s[nt][1]));
            vm1 = fmaxf(vm1, fmaxf(s[nt][2], s[nt][3]));
        }
        vm0 = fmaxf(vm0, __shfl_xor_sync(0xffffffff, vm0, 1));
        vm0 = fmaxf(vm0, __shfl_xor_sync(0xffffffff, vm0, 2));
        vm1 = fmaxf(vm1, __shfl_xor_sync(0xffffffff, vm1, 1));
        vm1 = fmaxf(vm1, __shfl_xor_sync(0xffffffff, vm1, 2));

        const float mn0 = fmaxf(m0, vm0), mn1 = fmaxf(m1, vm1);
        const float al0 = __expf(m0 - mn0), al1 = __expf(m1 - mn1);
        m0 = mn0; m1 = mn1;

        const int pr0 = (l >> 2), pc = (l & 3) * 2;
        float rs0 = 0.f, rs1 = 0.f;
#pragma unroll
        for (int nt = 0; nt < 8; nt++) {
            float p00 = __expf(s[nt][0] - mn0), p01 = __expf(s[nt][1] - mn0);
            float p10 = __expf(s[nt][2] - mn1), p11 = __expf(s[nt][3] - mn1);
            rs0 += p00 + p01; rs1 += p10 + p11;
            __half h00, l00h, h01, l01h, h10, l10h, h11, l11h;
            split2h(p00, h00, l00h); split2h(p01, h01, l01h);
            split2h(p10, h10, l10h); split2h(p11, h11, l11h);
            uint32_t hi0 = pack2h(h00, h01), lo0 = pack2h(l00h, l01h);
            uint32_t hi1 = pack2h(h10, h11), lo1 = pack2h(l10h, l11h);
            const int c = nt * 8 + pc;
            char* row0 = sPw + pr0 * ARSV;
            char* row1 = sPw + (pr0 + 8) * ARSV;
            *(uint32_t*)(row0 + c * 2)         = hi0;
            *(uint32_t*)(row0 + (64 + c) * 2)  = hi0;
            *(uint32_t*)(row0 + (128 + c) * 2) = lo0;
            *(uint32_t*)(row1 + c * 2)         = hi1;
            *(uint32_t*)(row1 + (64 + c) * 2)  = hi1;
            *(uint32_t*)(row1 + (128 + c) * 2) = lo1;
            o[nt][0] *= al0; o[nt][1] *= al0;
            o[nt][2] *= al1; o[nt][3] *= al1;
        }
        rs0 += __shfl_xor_sync(0xffffffff, rs0, 1);
        rs0 += __shfl_xor_sync(0xffffffff, rs0, 2);
        rs1 += __shfl_xor_sync(0xffffffff, rs1, 1);
        rs1 += __shfl_xor_sync(0xffffffff, rs1, 2);
        l0 = l0 * al0 + rs0;
        l1 = l1 * al1 + rs1;
        __syncwarp();

        // ---- O += P Vt^T, K=192 ----
#pragma unroll
        for (int ks = 0; ks < 12; ks++) {
            uint32_t af[4], bf[4][4];
            LDSM_X4(af[0], af[1], af[2], af[3], aP + ks * 32);
#pragma unroll
            for (int g = 0; g < 4; g++)
                LDSM_X4(bf[g][0], bf[g][1], bf[g][2], bf[g][3],
                        bV + g * (16 * ARSV) + ks * 32);
#pragma unroll
            for (int nt = 0; nt < 8; nt++)
                mma16816(o[nt], af, bf[nt >> 1][(nt & 1) * 2], bf[nt >> 1][(nt & 1) * 2 + 1]);
        }
    }

    // epilogue: write split Oc [hi | lo]
    const float inv0 = 1.f / l0, inv1 = 1.f / l1;
    const int r0 = qb * 64 + wid * 16 + (l >> 2);
    const int c0 = h * 64 + (l & 3) * 2;
#pragma unroll
    for (int nt = 0; nt < 8; nt++) {
        const int c = c0 + nt * 8;
#pragma unroll
        for (int rr = 0; rr < 2; rr++) {
            const float inv = rr ? inv1 : inv0;
            const size_t rowb = (size_t)(b * SEQ + r0 + rr * 8) * KTOT;
            __half hx, lx, hy, ly;
            split2h(o[nt][rr * 2 + 0] * inv, hx, lx);
            split2h(o[nt][rr * 2 + 1] * inv, hy, ly);
            *(uint32_t*)(Oc + rowb + c)        = pack2h(hx, hy);
            *(uint32_t*)(Oc + rowb + 1024 + c) = pack2h(lx, ly);
        }
    }
}

// ---------------- launcher ----------------
extern "C" void kernel_launch(void* const* d_in, const int* in_sizes, int n_in,
                              void* d_out, int out_size)
{
    const float* X  = (const float*)d_in[0];
    const float* Wq = (const float*)d_in[1];
    const float* Wk = (const float*)d_in[2];
    const float* Wv = (const float*)d_in[3];
    const float* Wo = (const float*)d_in[4];
    const unsigned char* mask = (const unsigned char*)d_in[5];
    float* out = (float*)d_out;

    float* Vb;
    __half *Xc, *Oc, *Wqkv, *Woc, *Qa, *Ka, *Va;
    cudaGetSymbolAddress((void**)&Vb, g_V);
    cudaGetSymbolAddress((void**)&Xc, g_Xc);
    cudaGetSymbolAddress((void**)&Oc, g_Oc);
    cudaGetSymbolAddress((void**)&Wqkv, g_Wqkv);
    cudaGetSymbolAddress((void**)&Woc, g_Wo);
    cudaGetSymbolAddress((void**)&Qa, g_Qa);
    cudaGetSymbolAddress((void**)&Ka, g_Ka);
    cudaGetSymbolAddress((void**)&Va, g_Va);

    cudaFuncSetAttribute(gemm_mma<true>,  cudaFuncAttributeMaxDynamicSharedMemorySize, SM_TOTAL);
    cudaFuncSetAttribute(gemm_mma<false>, cudaFuncAttributeMaxDynamicSharedMemorySize, SM_TOTAL);
    cudaFuncSetAttribute(attn_mma, cudaFuncAttributeMaxDynamicSharedMemorySize, ASM_TOTAL);

    // launch order chosen so ncu (-s 5 -c 1) captures the fused QKV GEMM (#6)
    build_block_mask<<<1, 1024>>>(mask);                                          // 1
    conv_act<<<(MROWS * DIM + 255) / 256, 256>>>(X, Xc, MROWS);                   // 2
    conv_wgt2<<<(2 * DIM * DIM + 255) / 256, 256>>>(Wq, Wk, Wqkv,
                                                    Wqkv + (size_t)DIM * KTOT);   // 3
    conv_wgt<<<(DIM * DIM + 255) / 256, 256>>>(Wv, Wqkv + 2 * (size_t)DIM * KTOT);// 4
    conv_wgt<<<(DIM * DIM + 255) / 256, 256>>>(Wo, Woc);                          // 5

    dim3 qkvgrid(3 * DIM / TN, MROWS / TM);   // (24, 32)
    gemm_mma<true><<<qkvgrid, 256, SM_TOTAL>>>(Xc, Wqkv, Qa, Ka, Vb, nullptr);    // 6

    conv_vt<<<BATCH * NH * NBLK, 128>>>(Vb, Va);                                  // 7

    dim3 agrid(NBLK, NH, BATCH);
    attn_mma<<<agrid, 128, ASM_TOTAL>>>(Qa, Ka, Va, Oc);                          // 8

    dim3 ogrid(DIM / TN, MROWS / TM);         // (8, 32)
    gemm_mma<false><<<ogrid, 256, SM_TOTAL>>>(Oc, Woc, nullptr, nullptr, nullptr, out); // 9
}

// round 8
// speedup vs baseline: 3.7858x; 1.0433x over previous
#include <cuda_runtime.h>
#include <cuda_fp16.h>
#include <math.h>
#include <stdint.h>

#define BATCH 2
#define SEQ   2048
#define DIM   1024
#define NH    16
#define HD    64
#define NBLK  32
#define BS    64
#define MROWS (BATCH * SEQ)        // 4096
#define KTOT  2048                 // 2 x 1024 fp16 split
#define KCH   64
#define NCHUNK (KTOT / KCH)        // 32
#define TM    128
#define TN    128
#define RSB   144
#define STAGE 18432
#define NSTG  3
#define SM_TOTAL (2 * NSTG * STAGE)   // 110592

// attention smem: 6 tiles (Q, P, K0, K1, V0, V1) of 64 rows x 272B
#define ARS   272
#define ATILE (64 * ARS)           // 17408
#define ASM_TOTAL (6 * ATILE)      // 104448

// ---------------- device scratch ----------------
__device__ float  g_V[MROWS * DIM];
__device__ __half g_Xc[(size_t)MROWS * KTOT];
__device__ __half g_Oc[(size_t)MROWS * KTOT];
__device__ __half g_Wqkv[(size_t)3 * DIM * KTOT];
__device__ __half g_Wo[(size_t)DIM * KTOT];
__device__ __half g_Qa[(size_t)BATCH * NH * SEQ * 128];   // [hi|lo]
__device__ __half g_Ka[(size_t)BATCH * NH * SEQ * 128];   // [hi|hi]
__device__ __half g_Va[(size_t)BATCH * NH * NBLK * 64 * 128]; // Vt [d,128j] = [hi|hi]
__device__ unsigned char g_bm[NBLK * NBLK];

// ---------------- helpers ----------------
__device__ __forceinline__ uint32_t smem_u32(const void* p) {
    uint32_t a;
    asm("{ .reg .u64 t; cvta.to.shared.u64 t, %1; cvt.u32.u64 %0, t; }" : "=r"(a) : "l"(p));
    return a;
}
#define LDSM_X4(r0, r1, r2, r3, addr) \
    asm volatile("ldmatrix.sync.aligned.m8n8.x4.shared.b16 {%0,%1,%2,%3}, [%4];" \
        : "=r"(r0), "=r"(r1), "=r"(r2), "=r"(r3) : "r"(addr))
#define CP16(saddr, gptr) \
    asm volatile("cp.async.cg.shared.global [%0], [%1], 16;" :: "r"(saddr), "l"(gptr))
#define CP_COMMIT() asm volatile("cp.async.commit_group;" ::: "memory")
#define CP_WAIT(n)  asm volatile("cp.async.wait_group %0;" :: "n"(n) : "memory")

__device__ __forceinline__ void mma16816(float* c, const uint32_t* a, uint32_t b0, uint32_t b1) {
    asm volatile("mma.sync.aligned.m16n8k16.row.col.f32.f16.f16.f32 "
        "{%0,%1,%2,%3}, {%4,%5,%6,%7}, {%8,%9}, {%0,%1,%2,%3};"
        : "+f"(c[0]), "+f"(c[1]), "+f"(c[2]), "+f"(c[3])
        : "r"(a[0]), "r"(a[1]), "r"(a[2]), "r"(a[3]), "r"(b0), "r"(b1));
}
__device__ __forceinline__ void split2h(float x, __half& h, __half& l) {
    h = __float2half_rn(x);
    l = __float2half_rn(x - __half2float(h));
}
__device__ __forceinline__ uint32_t pack2h(__half a, __half b) {
    return (uint32_t)__half_as_ushort(a) | ((uint32_t)__half_as_ushort(b) << 16);
}

// ---------------- mask build (dtype-agnostic) ----------------
__global__ void build_block_mask(const unsigned char* __restrict__ m)
{
    const unsigned char b1 = m[1];
    int esz = (b1 == 0) ? 4 : (b1 == 1 ? 1 : 2);
    int idx = blockIdx.x * blockDim.x + threadIdx.x;
    if (idx >= NBLK * NBLK) return;
    int qb = idx / NBLK, kb = idx % NBLK;
    size_t elem = (size_t)(qb * BS) * SEQ + (size_t)kb * BS;
    bool allowed;
    if (esz == 1)      allowed = m[elem] != 0;
    else if (esz == 2) allowed = ((const unsigned short*)m)[elem] != 0;
    else               allowed = ((const unsigned int*)m)[elem] != 0;
    g_bm[idx] = allowed ? 1 : 0;
}

// ---------------- fp32 -> fp16 conversions ----------------
__global__ void conv_act(const float* __restrict__ X, __half* __restrict__ out, int rows)
{
    int i = blockIdx.x * blockDim.x + threadIdx.x;
    if (i >= rows * DIM) return;
    int r = i >> 10, c = i & 1023;
    __half h, l; split2h(X[i], h, l);
    size_t base = (size_t)r * KTOT;
    out[base + c] = h; out[base + 1024 + c] = l;
}
// all four weights in one launch: Wq,Wk,Wv -> Wqkv segments, Wo -> Woc. Pattern [hi|hi].
__global__ void conv_wgt_all(const float* __restrict__ Wq, const float* __restrict__ Wk,
                             const float* __restrict__ Wv, const float* __restrict__ Wo,
                             __half* __restrict__ Wqkv, __half* __restrict__ Woc)
{
    int i = blockIdx.x * blockDim.x + threadIdx.x;
    if (i >= 4 * DIM * DIM) return;
    int w = i >> 20;                       // DIM*DIM == 2^20
    int j = i & (DIM * DIM - 1);
    const float* W = (w == 0) ? Wq : (w == 1) ? Wk : (w == 2) ? Wv : Wo;
    __half* out = (w < 3) ? (Wqkv + (size_t)w * DIM * KTOT) : Woc;
    int r = j >> 10, c = j & 1023;
    __half h = __float2half_rn(W[j]);
    size_t base = (size_t)r * KTOT;
    out[base + c] = h; out[base + 1024 + c] = h;
}
// V transpose per (b,h,kb): Vt[d, 128j] = [hi|hi]
__global__ void conv_vt(const float* __restrict__ V, __half* __restrict__ Va)
{
    __shared__ float tile[64][65];
    int bid = blockIdx.x;
    int kb = bid & 31, bh = bid >> 5;
    int b = bh >> 4, h = bh & 15;
    int tid = threadIdx.x;
    for (int i = tid; i < 4096; i += 128) {
        int t = i >> 6, d = i & 63;
        tile[t][d] = V[((size_t)(b * SEQ + kb * 64 + t)) * DIM + h * 64 + d];
    }
    __syncthreads();
    for (int i = tid; i < 4096; i += 128) {
        int d = i >> 6, j = i & 63;
        __half hh = __float2half_rn(tile[j][d]);
        size_t base = ((size_t)bid * 64 + d) * 128;
        Va[base + j] = hh; Va[base + 64 + j] = hh;
    }
}

// ---------------- pipelined mma.sync GEMM ----------------
// QKV=true: B is Wqkv [3072,2048]; epilogue by column segment:
//   n<1024 -> Qa [hi|lo];  n<2048 -> Ka [hi|hi];  else -> V fp32.
// QKV=false: plain fp32 C [MROWS, DIM].
template<bool QKV>
__global__ void __launch_bounds__(256, 2)
gemm_mma(const __half* __restrict__ A, const __half* __restrict__ Bw,
         __half* __restrict__ Qa, __half* __restrict__ Ka,
         float* __restrict__ Vout, float* __restrict__ C)
{
    extern __shared__ char dsm[];
    const uint32_t sb = smem_u32(dsm);
    const int tid = threadIdx.x;
    const int wid = tid >> 5, l = tid & 31;
    const int wm = wid >> 2, wn = wid & 3;
    const int m0 = blockIdx.y * TM, n0 = blockIdx.x * TN;

    const int r = tid >> 1;
    const int cbB = (tid & 1) * 64;
    const int cbE = (tid & 1) * 32;
    const __half* Ag = A + (size_t)(m0 + r) * KTOT + cbE;
    const __half* Bg = Bw + (size_t)(n0 + r) * KTOT + cbE;
    const uint32_t sa_row = sb + r * RSB + cbB;
    const uint32_t sb_row = sb + NSTG * STAGE + r * RSB + cbB;

    float acc[4][4][4];
#pragma unroll
    for (int i = 0; i < 4; i++)
#pragma unroll
        for (int j = 0; j < 4; j++)
#pragma unroll
            for (int q = 0; q < 4; q++) acc[i][j][q] = 0.f;

    const uint32_t a_off = (uint32_t)((l & 15) * RSB + (l >> 4) * 16);
    const uint32_t b_off = (uint32_t)(((l & 7) + ((l >> 4) & 1) * 8) * RSB + ((l >> 3) & 1) * 16);

#pragma unroll
    for (int s = 0; s < NSTG - 1; s++) {
#pragma unroll
        for (int q = 0; q < 4; q++) {
            CP16(sa_row + s * STAGE + q * 16, Ag + s * KCH + q * 8);
            CP16(sb_row + s * STAGE + q * 16, Bg + s * KCH + q * 8);
        }
        CP_COMMIT();
    }

    for (int i = 0; i < NCHUNK; i++) {
        if (i < NCHUNK - 1) CP_WAIT(1); else CP_WAIT(0);
        __syncthreads();

        if (i + NSTG - 1 < NCHUNK) {
            const int s = (i + NSTG - 1) % NSTG;
            const int k0 = (i + NSTG - 1) * KCH;
#pragma unroll
            for (int q = 0; q < 4; q++) {
                CP16(sa_row + s * STAGE + q * 16, Ag + k0 + q * 8);
                CP16(sb_row + s * STAGE + q * 16, Bg + k0 + q * 8);
            }
        }
        CP_COMMIT();

        const int slot = i % NSTG;
        const uint32_t abase = sb + slot * STAGE + (uint32_t)(wm * 64) * RSB + a_off;
        const uint32_t bbase = sb + NSTG * STAGE + slot * STAGE + (uint32_t)(wn * 32) * RSB + b_off;
#pragma unroll
        for (int ks = 0; ks < 4; ks++) {
            uint32_t af[4][4], bf[2][4];
#pragma unroll
            for (int mt = 0; mt < 4; mt++)
                LDSM_X4(af[mt][0], af[mt][1], af[mt][2], af[mt][3],
                        abase + mt * (16 * RSB) + ks * 32);
#pragma unroll
            for (int g = 0; g < 2; g++)
                LDSM_X4(bf[g][0], bf[g][1], bf[g][2], bf[g][3],
                        bbase + g * (16 * RSB) + ks * 32);
#pragma unroll
            for (int mt = 0; mt < 4; mt++)
#pragma unroll
                for (int nt = 0; nt < 4; nt++)
                    mma16816(acc[mt][nt], af[mt], bf[nt >> 1][(nt & 1) * 2],
                             bf[nt >> 1][(nt & 1) * 2 + 1]);
        }
    }

    const int mode = QKV ? (n0 >> 10) : 3;   // 0=Q, 1=K, 2=V, 3=fp32 C
#pragma unroll
    for (int mt = 0; mt < 4; mt++) {
#pragma unroll
        for (int nt = 0; nt < 4; nt++) {
            const int mr = m0 + wm * 64 + mt * 16 + (l >> 2);
            const int nc = n0 + wn * 32 + nt * 8 + (l & 3) * 2;
            if (mode == 3) {
                *(float2*)(C + (size_t)mr * DIM + nc) =
                    make_float2(acc[mt][nt][0], acc[mt][nt][1]);
                *(float2*)(C + (size_t)(mr + 8) * DIM + nc) =
                    make_float2(acc[mt][nt][2], acc[mt][nt][3]);
            } else if (mode == 2) {
                const int col = nc - 2048;
                *(float2*)(Vout + (size_t)mr * DIM + col) =
                    make_float2(acc[mt][nt][0], acc[mt][nt][1]);
                *(float2*)(Vout + (size_t)(mr + 8) * DIM + col) =
                    make_float2(acc[mt][nt][2], acc[mt][nt][3]);
            } else {
                const int cl = nc & 1023;
                const int hh = cl >> 6, d = cl & 63;
                __half* dst = (mode == 0) ? Qa : Ka;
#pragma unroll
                for (int rr = 0; rr < 2; rr++) {
                    const int row = mr + rr * 8;
                    const int bb = row >> 11, t = row & 2047;
                    const size_t base = ((size_t)(bb * NH + hh) * SEQ + t) * 128;
                    __half hx, lx, hy, ly;
                    split2h(acc[mt][nt][rr * 2 + 0], hx, lx);
                    split2h(acc[mt][nt][rr * 2 + 1], hy, ly);
                    *(uint32_t*)(dst + base + d) = pack2h(hx, hy);
                    *(uint32_t*)(dst + base + 64 + d) =
                        (mode == 0) ? pack2h(lx, ly) : pack2h(hx, hy);
                }
            }
        }
    }
}

// ---------------- tensor-core block-sparse flash attention (fp16, all K=128) ----------------
// QK: [qhi|qlo] x [khi|khi].  PV: [Phi|Plo] x [vhi|vhi].
// K/V tiles double-buffered with one-block cp.async lookahead.
__global__ void __launch_bounds__(128, 2)
attn_mma(const __half* __restrict__ Qa, const __half* __restrict__ Ka,
         const __half* __restrict__ Va, __half* __restrict__ Oc)
{
    extern __shared__ char sm[];
    const uint32_t sb = smem_u32(sm);
    const uint32_t oQ = 0, oP = ATILE, oK = 2 * ATILE, oV = 4 * ATILE;

    const int tid = threadIdx.x, wid = tid >> 5, l = tid & 31;
    const int qb = blockIdx.x, h = blockIdx.y, b = blockIdx.z;
    const size_t bh = (size_t)(b * NH + h);

    // allowed-block bitmask
    uint32_t am = 0;
#pragma unroll
    for (int kb = 0; kb < NBLK; kb++)
        am |= (g_bm[qb * NBLK + kb] ? 1u : 0u) << kb;

    // cp.async staging coords: thread covers row r, 8 x 16B chunks (half row)
    const int r = tid >> 1;
    const int cq = (tid & 1) * 8;
    const uint32_t srow = (uint32_t)(r * ARS + cq * 16);

    // prologue: Q + first K/V block (group 0)
    {
        const __half* Qg = Qa + (bh * SEQ + qb * 64 + r) * 128 + cq * 8;
#pragma unroll
        for (int q = 0; q < 8; q++) CP16(sb + oQ + srow + q * 16, Qg + q * 8);
    }
    int kb_cur = __ffs(am) - 1;          // always >= 0 (col 0 is global)
    am &= am - 1;
    {
        const __half* Kg = Ka + (bh * SEQ + kb_cur * 64 + r) * 128 + cq * 8;
        const __half* Vg = Va + ((bh * NBLK + kb_cur) * 64 + r) * 128 + cq * 8;
#pragma unroll
        for (int q = 0; q < 8; q++) {
            CP16(sb + oK + srow + q * 16, Kg + q * 8);
            CP16(sb + oV + srow + q * 16, Vg + q * 8);
        }
    }
    CP_COMMIT();

    float o[8][4];
#pragma unroll
    for (int nt = 0; nt < 8; nt++)
#pragma unroll
        for (int q = 0; q < 4; q++) o[nt][q] = 0.f;
    float m0 = -INFINITY, m1 = -INFINITY, l0 = 0.f, l1 = 0.f;

    const uint32_t a_off = (uint32_t)((l & 15) * ARS + (l >> 4) * 16);
    const uint32_t b_off = (uint32_t)(((l & 7) + ((l >> 4) & 1) * 8) * ARS + ((l >> 3) & 1) * 16);
    const uint32_t aQ = sb + oQ + (uint32_t)(wid * 16) * ARS + a_off;
    const uint32_t aP = sb + oP + (uint32_t)(wid * 16) * ARS + a_off;
    char* sPw = sm + oP + (size_t)(wid * 16) * ARS;
    const float scale = 0.125f;

    int sbuf = 0;
    while (kb_cur >= 0) {
        const int kb_nxt = am ? (__ffs(am) - 1) : -1;
        am &= am - 1;

        CP_WAIT(0);
        __syncthreads();                 // data visible to all; prev buffer free

        if (kb_nxt >= 0) {
            const int s = sbuf ^ 1;
            const __half* Kg = Ka + (bh * SEQ + kb_nxt * 64 + r) * 128 + cq * 8;
            const __half* Vg = Va + ((bh * NBLK + kb_nxt) * 64 + r) * 128 + cq * 8;
#pragma unroll
            for (int q = 0; q < 8; q++) {
                CP16(sb + oK + s * ATILE + srow + q * 16, Kg + q * 8);
                CP16(sb + oV + s * ATILE + srow + q * 16, Vg + q * 8);
            }
        }
        CP_COMMIT();

        const uint32_t bK = sb + oK + sbuf * ATILE + b_off;
        const uint32_t bV = sb + oV + sbuf * ATILE + b_off;

        // ---- S = Q K^T, K=128 ----
        float s[8][4];
#pragma unroll
        for (int nt = 0; nt < 8; nt++)
#pragma unroll
            for (int q = 0; q < 4; q++) s[nt][q] = 0.f;
#pragma unroll
        for (int ks = 0; ks < 8; ks++) {
            uint32_t af[4], bf[4][4];
            LDSM_X4(af[0], af[1], af[2], af[3], aQ + ks * 32);
#pragma unroll
            for (int g = 0; g < 4; g++)
                LDSM_X4(bf[g][0], bf[g][1], bf[g][2], bf[g][3],
                        bK + g * (16 * ARS) + ks * 32);
#pragma unroll
            for (int nt = 0; nt < 8; nt++)
                mma16816(s[nt], af, bf[nt >> 1][(nt & 1) * 2], bf[nt >> 1][(nt & 1) * 2 + 1]);
        }

        // ---- online softmax + P split [Phi|Plo] into smem ----
        float vm0 = -INFINITY, vm1 = -INFINITY;
#pragma unroll
        for (int nt = 0; nt < 8; nt++) {
#pragma unroll
            for (int q = 0; q < 4; q++) s[nt][q] *= scale;
            vm0 = fmaxf(vm0, fmaxf(s[nt][0], s[nt][1]));
            vm1 = fmaxf(vm1, fmaxf(s[nt][2], s[nt][3]));
        }
        vm0 = fmaxf(vm0, __shfl_xor_sync(0xffffffff, vm0, 1));
        vm0 = fmaxf(vm0, __shfl_xor_sync(0xffffffff, vm0, 2));
        vm1 = fmaxf(vm1, __shfl_xor_sync(0xffffffff, vm1, 1));
        vm1 = fmaxf(vm1, __shfl_xor_sync(0xffffffff, vm1, 2));

        const float mn0 = fmaxf(m0, vm0), mn1 = fmaxf(m1, vm1);
        const float al0 = __expf(m0 - mn0), al1 = __expf(m1 - mn1);
        m0 = mn0; m1 = mn1;

        const int pr0 = (l >> 2), pc = (l & 3) * 2;
        float rs0 = 0.f, rs1 = 0.f;
#pragma unroll
        for (int nt = 0; nt < 8; nt++) {
            float p00 = __expf(s[nt][0] - mn0), p01 = __expf(s[nt][1] - mn0);
            float p10 = __expf(s[nt][2] - mn1), p11 = __expf(s[nt][3] - mn1);
            rs0 += p00 + p01; rs1 += p10 + p11;
            __half h00, l00h, h01, l01h, h10, l10h, h11, l11h;
            split2h(p00, h00, l00h); split2h(p01, h01, l01h);
            split2h(p10, h10, l10h); split2h(p11, h11, l11h);
            const int c = nt * 8 + pc;
            char* row0 = sPw + pr0 * ARS;
            char* row1 = sPw + (pr0 + 8) * ARS;
            *(uint32_t*)(row0 + c * 2)        = pack2h(h00, h01);
            *(uint32_t*)(row0 + (64 + c) * 2) = pack2h(l00h, l01h);
            *(uint32_t*)(row1 + c * 2)        = pack2h(h10, h11);
            *(uint32_t*)(row1 + (64 + c) * 2) = pack2h(l10h, l11h);
            o[nt][0] *= al0; o[nt][1] *= al0;
            o[nt][2] *= al1; o[nt][3] *= al1;
        }
        rs0 += __shfl_xor_sync(0xffffffff, rs0, 1);
        rs0 += __shfl_xor_sync(0xffffffff, rs0, 2);
        rs1 += __shfl_xor_sync(0xffffffff, rs1, 1);
        rs1 += __shfl_xor_sync(0xffffffff, rs1, 2);
        l0 = l0 * al0 + rs0;
        l1 = l1 * al1 + rs1;
        __syncwarp();

        // ---- O += P Vt^T, K=128 ----
#pragma unroll
        for (int ks = 0; ks < 8; ks++) {
            uint32_t af[4], bf[4][4];
            LDSM_X4(af[0], af[1], af[2], af[3], aP + ks * 32);
#pragma unroll
            for (int g = 0; g < 4; g++)
                LDSM_X4(bf[g][0], bf[g][1], bf[g][2], bf[g][3],
                        bV + g * (16 * ARS) + ks * 32);
#pragma unroll
            for (int nt = 0; nt < 8; nt++)
                mma16816(o[nt], af, bf[nt >> 1][(nt & 1) * 2], bf[nt >> 1][(nt & 1) * 2 + 1]);
        }

        kb_cur = kb_nxt;
        sbuf ^= 1;
    }

    // epilogue: write split Oc [hi | lo]
    const float inv0 = 1.f / l0, inv1 = 1.f / l1;
    const int r0 = qb * 64 + wid * 16 + (l >> 2);
    const int c0 = h * 64 + (l & 3) * 2;
#pragma unroll
    for (int nt = 0; nt < 8; nt++) {
        const int c = c0 + nt * 8;
#pragma unroll
        for (int rr = 0; rr < 2; rr++) {
            const float inv = rr ? inv1 : inv0;
            const size_t rowb = (size_t)(b * SEQ + r0 + rr * 8) * KTOT;
            __half hx, lx, hy, ly;
            split2h(o[nt][rr * 2 + 0] * inv, hx, lx);
            split2h(o[nt][rr * 2 + 1] * inv, hy, ly);
            *(uint32_t*)(Oc + rowb + c)        = pack2h(hx, hy);
            *(uint32_t*)(Oc + rowb + 1024 + c) = pack2h(lx, ly);
        }
    }
}

// ---------------- launcher ----------------
extern "C" void kernel_launch(void* const* d_in, const int* in_sizes, int n_in,
                              void* d_out, int out_size)
{
    const float* X  = (const float*)d_in[0];
    const float* Wq = (const float*)d_in[1];
    const float* Wk = (const float*)d_in[2];
    const float* Wv = (const float*)d_in[3];
    const float* Wo = (const float*)d_in[4];
    const unsigned char* mask = (const unsigned char*)d_in[5];
    float* out = (float*)d_out;

    float* Vb;
    __half *Xc, *Oc, *Wqkv, *Woc, *Qa, *Ka, *Va;
    cudaGetSymbolAddress((void**)&Vb, g_V);
    cudaGetSymbolAddress((void**)&Xc, g_Xc);
    cudaGetSymbolAddress((void**)&Oc, g_Oc);
    cudaGetSymbolAddress((void**)&Wqkv, g_Wqkv);
    cudaGetSymbolAddress((void**)&Woc, g_Wo);
    cudaGetSymbolAddress((void**)&Qa, g_Qa);
    cudaGetSymbolAddress((void**)&Ka, g_Ka);
    cudaGetSymbolAddress((void**)&Va, g_Va);

    cudaFuncSetAttribute(gemm_mma<true>,  cudaFuncAttributeMaxDynamicSharedMemorySize, SM_TOTAL);
    cudaFuncSetAttribute(gemm_mma<false>, cudaFuncAttributeMaxDynamicSharedMemorySize, SM_TOTAL);
    cudaFuncSetAttribute(attn_mma, cudaFuncAttributeMaxDynamicSharedMemorySize, ASM_TOTAL);

    build_block_mask<<<1, 1024>>>(mask);                                          // 1
    conv_act<<<(MROWS * DIM + 255) / 256, 256>>>(X, Xc, MROWS);                   // 2
    conv_wgt_all<<<(4 * DIM * DIM + 255) / 256, 256>>>(Wq, Wk, Wv, Wo, Wqkv, Woc);// 3

    dim3 qkvgrid(3 * DIM / TN, MROWS / TM);   // (24, 32)
    gemm_mma<true><<<qkvgrid, 256, SM_TOTAL>>>(Xc, Wqkv, Qa, Ka, Vb, nullptr);    // 4

    conv_vt<<<BATCH * NH * NBLK, 128>>>(Vb, Va);                                  // 5

    dim3 agrid(NBLK, NH, BATCH);
    attn_mma<<<agrid, 128, ASM_TOTAL>>>(Qa, Ka, Va, Oc);                          // 6

    dim3 ogrid(DIM / TN, MROWS / TM);         // (8, 32)
    gemm_mma<false><<<ogrid, 256, SM_TOTAL>>>(Oc, Woc, nullptr, nullptr, nullptr, out); // 7
}